// round 5
// baseline (speedup 1.0000x reference)
#include <cuda_runtime.h>
#include <math.h>
#include <stdint.h>

#define D_    768
#define H_    12
#define HD_   64
#define DFF_  3072
#define MAXT  8192
#define SMAX_ 1024

// ---------------- scratch (no allocations allowed) ----------------
__device__ float g_xn  [(size_t)MAXT * D_];
__device__ float g_qkv [(size_t)MAXT * 3 * D_];
__device__ float g_attn[(size_t)MAXT * D_];
__device__ float g_x2  [(size_t)MAXT * D_];
__device__ float g_mid [(size_t)MAXT * DFF_];
__device__ float g_WqkvT[(size_t)3 * D_ * D_];
__device__ float g_WoT  [(size_t)D_ * D_];
__device__ float g_W1T  [(size_t)DFF_ * D_];
__device__ float g_W2T  [(size_t)D_ * DFF_];

// ---------------- helpers ----------------
__device__ __forceinline__ uint32_t smem_u32(const void* p) {
    uint32_t a;
    asm("{ .reg .u64 t; cvta.to.shared.u64 t, %1; cvt.u32.u64 %0, t; }" : "=r"(a) : "l"(p));
    return a;
}
__device__ __forceinline__ float rna_tf32(float x) {
    uint32_t u;
    asm("cvt.rna.tf32.f32 %0, %1;" : "=r"(u) : "f"(x));
    return __uint_as_float(u);
}
#define CP_ASYNC16(dst, src) \
    asm volatile("cp.async.cg.shared.global [%0], [%1], 16;" :: "r"(dst), "l"(src) : "memory")
#define CP_COMMIT() asm volatile("cp.async.commit_group;" ::: "memory")
#define CP_WAIT(n)  asm volatile("cp.async.wait_group %0;" :: "n"(n) : "memory")

__device__ __forceinline__ void mma_tf32(float* c, const uint32_t* a, const uint32_t* b) {
    asm volatile(
        "mma.sync.aligned.m16n8k8.row.col.f32.tf32.tf32.f32 "
        "{%0,%1,%2,%3}, {%4,%5,%6,%7}, {%8,%9}, {%0,%1,%2,%3};"
        : "+f"(c[0]), "+f"(c[1]), "+f"(c[2]), "+f"(c[3])
        : "r"(a[0]), "r"(a[1]), "r"(a[2]), "r"(a[3]), "r"(b[0]), "r"(b[1]));
}

// ---------------- transpose + tf32 round: WT[n][k] = rna(W[k][n]) ----------------
__global__ void __launch_bounds__(256) transpose_rna(const float* __restrict__ W,
                                                     float* __restrict__ WT,
                                                     int K, int N) {
    __shared__ float tile[32][33];
    int tx = threadIdx.x, ty = threadIdx.y;
    int n0 = blockIdx.x * 32, k0 = blockIdx.y * 32;
#pragma unroll
    for (int i = 0; i < 4; i++)
        tile[ty + 8 * i][tx] = W[(size_t)(k0 + ty + 8 * i) * N + n0 + tx];
    __syncthreads();
#pragma unroll
    for (int i = 0; i < 4; i++)
        WT[(size_t)(n0 + ty + 8 * i) * K + k0 + tx] = rna_tf32(tile[tx][ty + 8 * i]);
}

// ---------------- LayerNorm (tf32-rounded output) ----------------
__global__ void __launch_bounds__(256) ln_kernel(const float* __restrict__ x,
                                                 const float* __restrict__ g,
                                                 const float* __restrict__ be,
                                                 float* __restrict__ y) {
    int t = blockIdx.x;
    const float* xr = x + (size_t)t * D_;
    float*       yr = y + (size_t)t * D_;
    int tid = threadIdx.x;
    float v0 = xr[tid], v1 = xr[tid + 256], v2 = xr[tid + 512];
    float s  = v0 + v1 + v2;
    float s2 = v0 * v0 + v1 * v1 + v2 * v2;
    __shared__ float sh1[256], sh2[256];
    sh1[tid] = s; sh2[tid] = s2;
    __syncthreads();
    for (int o = 128; o > 0; o >>= 1) {
        if (tid < o) { sh1[tid] += sh1[tid + o]; sh2[tid] += sh2[tid + o]; }
        __syncthreads();
    }
    float mu  = sh1[0] * (1.0f / D_);
    float var = sh2[0] * (1.0f / D_) - mu * mu;
    float r   = rsqrtf(var + 1e-6f);
    yr[tid]       = rna_tf32((v0 - mu) * r * g[tid]       + be[tid]);
    yr[tid + 256] = rna_tf32((v1 - mu) * r * g[tid + 256] + be[tid + 256]);
    yr[tid + 512] = rna_tf32((v2 - mu) * r * g[tid + 512] + be[tid + 512]);
}

// ---------------- tf32 mma.sync GEMM: C[M,N] = A[M,K] @ BT[N,K]^T + epi ----------
#define TS 20
template <int EPI>
__global__ void __launch_bounds__(128) tgemm(const float* __restrict__ A,
                                             const float* __restrict__ BT,
                                             const float* __restrict__ bias,
                                             const float* __restrict__ res,
                                             float* __restrict__ C,
                                             int M, int N, int K) {
    __shared__ float As[2][128 * TS];
    __shared__ float Bs[2][128 * TS];

    int tid = threadIdx.x;
    int lane = tid & 31, wid = tid >> 5;
    int warpM = wid >> 1, warpN = wid & 1;
    int g = lane >> 2, t4 = lane & 3;
    int bm = blockIdx.y * 128, bn = blockIdx.x * 128;

    const float* gA = A  + (size_t)bm * K;
    const float* gB = BT + (size_t)bn * K;

    int lrow = tid >> 2;
    int lc4  = tid & 3;

    float acc[4][8][4];
#pragma unroll
    for (int mf = 0; mf < 4; mf++)
#pragma unroll
        for (int nf = 0; nf < 8; nf++)
#pragma unroll
            for (int r = 0; r < 4; r++) acc[mf][nf][r] = 0.f;

    uint32_t sA0 = smem_u32(&As[0][0]), sB0 = smem_u32(&Bs[0][0]);
    int nc = K >> 4;

    {
        const float* a0 = gA + lc4 * 4;
        const float* b0 = gB + lc4 * 4;
#pragma unroll
        for (int i = 0; i < 4; i++) {
            int row = lrow + 32 * i;
            uint32_t off = (uint32_t)(row * TS + lc4 * 4) * 4;
            CP_ASYNC16(sA0 + off, a0 + (size_t)row * K);
            CP_ASYNC16(sB0 + off, b0 + (size_t)row * K);
        }
        CP_COMMIT();
    }

    for (int c = 0; c < nc; c++) {
        int st = c & 1;
        if (c + 1 < nc) {
            int k0 = (c + 1) << 4;
            uint32_t sa = sA0 + ((c + 1) & 1) * (128 * TS * 4);
            uint32_t sb = sB0 + ((c + 1) & 1) * (128 * TS * 4);
            const float* a0 = gA + k0 + lc4 * 4;
            const float* b0 = gB + k0 + lc4 * 4;
#pragma unroll
            for (int i = 0; i < 4; i++) {
                int row = lrow + 32 * i;
                uint32_t off = (uint32_t)(row * TS + lc4 * 4) * 4;
                CP_ASYNC16(sa + off, a0 + (size_t)row * K);
                CP_ASYNC16(sb + off, b0 + (size_t)row * K);
            }
            CP_COMMIT();
            CP_WAIT(1);
        } else {
            CP_WAIT(0);
        }
        __syncthreads();

        const float* as = &As[st][0];
        const float* bs = &Bs[st][0];
#pragma unroll
        for (int ko = 0; ko < 16; ko += 8) {
            uint32_t af[4][4];
#pragma unroll
            for (int mf = 0; mf < 4; mf++) {
                int r = warpM * 64 + mf * 16 + g;
                af[mf][0] = __float_as_uint(as[r * TS + ko + t4]);
                af[mf][1] = __float_as_uint(as[(r + 8) * TS + ko + t4]);
                af[mf][2] = __float_as_uint(as[r * TS + ko + t4 + 4]);
                af[mf][3] = __float_as_uint(as[(r + 8) * TS + ko + t4 + 4]);
            }
            uint32_t bf[8][2];
#pragma unroll
            for (int nf = 0; nf < 8; nf++) {
                int n = warpN * 64 + nf * 8 + g;
                bf[nf][0] = __float_as_uint(bs[n * TS + ko + t4]);
                bf[nf][1] = __float_as_uint(bs[n * TS + ko + t4 + 4]);
            }
#pragma unroll
            for (int mf = 0; mf < 4; mf++)
#pragma unroll
                for (int nf = 0; nf < 8; nf++)
                    mma_tf32(acc[mf][nf], af[mf], bf[nf]);
        }
        __syncthreads();
    }

#pragma unroll
    for (int mf = 0; mf < 4; mf++) {
        int r0 = bm + warpM * 64 + mf * 16 + g;
#pragma unroll
        for (int nf = 0; nf < 8; nf++) {
            int cc = bn + warpN * 64 + nf * 8 + t4 * 2;
            float b0 = bias[cc], b1 = bias[cc + 1];
            float v00 = acc[mf][nf][0] + b0, v01 = acc[mf][nf][1] + b1;
            float v10 = acc[mf][nf][2] + b0, v11 = acc[mf][nf][3] + b1;
            if (EPI == 1) {
                const float* rp0 = res + (size_t)r0 * N + cc;
                const float* rp1 = res + (size_t)(r0 + 8) * N + cc;
                v00 += rp0[0]; v01 += rp0[1];
                v10 += rp1[0]; v11 += rp1[1];
            }
            if (EPI == 2) {
                v00 = rna_tf32(0.5f * v00 * (1.0f + erff(v00 * 0.70710678118654752f)));
                v01 = rna_tf32(0.5f * v01 * (1.0f + erff(v01 * 0.70710678118654752f)));
                v10 = rna_tf32(0.5f * v10 * (1.0f + erff(v10 * 0.70710678118654752f)));
                v11 = rna_tf32(0.5f * v11 * (1.0f + erff(v11 * 0.70710678118654752f)));
            }
            *(float2*)(C + (size_t)r0 * N + cc)       = make_float2(v00, v01);
            *(float2*)(C + (size_t)(r0 + 8) * N + cc) = make_float2(v10, v11);
        }
    }
}

// ---------------- Ragged flash attention on tf32 mma.sync ------------------------
// grid (SMAX/64, H, B), 128 threads = 4 warps; warp w owns query rows w*16..+15.
// Per 64-key tile: S = Q@K^T (8x8 mmas), fragment softmax, P staged via smem,
// O += P@V with V transposed in smem. Smem stride 68 => conflict-free frag loads.
#define AS 68
__global__ void __launch_bounds__(128) attn_kernel(const float* __restrict__ qkv,
                                                   const int* __restrict__ cu,
                                                   float* __restrict__ out) {
    extern __shared__ float sm[];
    float* Qs  = sm;                // [64][AS]
    float* Ks  = sm + 64 * AS;      // [64][AS]  (key-major)
    float* VsT = sm + 2 * 64 * AS;  // [64][AS]  (dim-major: VsT[d][j])
    float* Ps  = sm + 3 * 64 * AS;  // [64][AS]

    int qt = blockIdx.x, h = blockIdx.y, b = blockIdx.z;
    int base = cu[b];
    int len  = cu[b + 1] - base;
    int q0   = qt * 64;
    if (q0 >= len) return;
    int nq = min(64, len - q0);

    int tid = threadIdx.x;
    int lane = tid & 31, wid = tid >> 5;
    int g = lane >> 2, t4 = lane & 3;
    int qw = wid * 16;              // warp's first query row (local)

    // load Q tile (scaled, rna-rounded)
    for (int idx = tid; idx < 64 * 64; idx += 128) {
        int qi = idx >> 6, d = idx & 63;
        Qs[qi * AS + d] = (qi < nq)
            ? rna_tf32(qkv[(size_t)(base + q0 + qi) * 2304 + h * 64 + d] * 0.125f)
            : 0.f;
    }

    float m0 = -1e30f, m1 = -1e30f, l0 = 0.f, l1 = 0.f;
    float oacc[8][4];
#pragma unroll
    for (int nf = 0; nf < 8; nf++)
#pragma unroll
        for (int r = 0; r < 4; r++) oacc[nf][r] = 0.f;

    for (int k0 = 0; k0 < len; k0 += 64) {
        int nk = min(64, len - k0);
        __syncthreads();   // Q ready (iter 0) / prev-iter K,V consumers done
        for (int idx = tid; idx < 64 * 64; idx += 128) {
            int j = idx >> 6, d = idx & 63;
            float kv = 0.f, vv = 0.f;
            if (j < nk) {
                size_t r = (size_t)(base + k0 + j) * 2304 + h * 64 + d;
                kv = rna_tf32(qkv[r + 768]);
                vv = rna_tf32(qkv[r + 1536]);
            }
            Ks[j * AS + d]  = kv;
            VsT[d * AS + j] = vv;
        }
        __syncthreads();

        // S = Q @ K^T : 8 key-frags x 8 k-steps
        float sacc[8][4];
#pragma unroll
        for (int nf = 0; nf < 8; nf++)
#pragma unroll
            for (int r = 0; r < 4; r++) sacc[nf][r] = 0.f;
#pragma unroll
        for (int kk = 0; kk < 64; kk += 8) {
            uint32_t af[4];
            af[0] = __float_as_uint(Qs[(qw + g) * AS + kk + t4]);
            af[1] = __float_as_uint(Qs[(qw + g + 8) * AS + kk + t4]);
            af[2] = __float_as_uint(Qs[(qw + g) * AS + kk + t4 + 4]);
            af[3] = __float_as_uint(Qs[(qw + g + 8) * AS + kk + t4 + 4]);
#pragma unroll
            for (int nf = 0; nf < 8; nf++) {
                uint32_t bf[2];
                bf[0] = __float_as_uint(Ks[(nf * 8 + g) * AS + kk + t4]);
                bf[1] = __float_as_uint(Ks[(nf * 8 + g) * AS + kk + t4 + 4]);
                mma_tf32(sacc[nf], af, bf);
            }
        }

        // mask invalid keys
#pragma unroll
        for (int nf = 0; nf < 8; nf++) {
            int j = nf * 8 + 2 * t4;
            if (j >= nk)     { sacc[nf][0] = -1e30f; sacc[nf][2] = -1e30f; }
            if (j + 1 >= nk) { sacc[nf][1] = -1e30f; sacc[nf][3] = -1e30f; }
        }

        // rows g (c0,c1) and g+8 (c2,c3): max over 8 frags then quad shuffle
        float tm0 = -1e30f, tm1 = -1e30f;
#pragma unroll
        for (int nf = 0; nf < 8; nf++) {
            tm0 = fmaxf(tm0, fmaxf(sacc[nf][0], sacc[nf][1]));
            tm1 = fmaxf(tm1, fmaxf(sacc[nf][2], sacc[nf][3]));
        }
        tm0 = fmaxf(tm0, __shfl_xor_sync(0xffffffffu, tm0, 1));
        tm0 = fmaxf(tm0, __shfl_xor_sync(0xffffffffu, tm0, 2));
        tm1 = fmaxf(tm1, __shfl_xor_sync(0xffffffffu, tm1, 1));
        tm1 = fmaxf(tm1, __shfl_xor_sync(0xffffffffu, tm1, 2));

        float nm0 = fmaxf(m0, tm0), nm1 = fmaxf(m1, tm1);
        float sc0 = __expf(m0 - nm0), sc1 = __expf(m1 - nm1);

        float ls0 = 0.f, ls1 = 0.f;
#pragma unroll
        for (int nf = 0; nf < 8; nf++) {
            float p0 = rna_tf32(__expf(sacc[nf][0] - nm0));
            float p1 = rna_tf32(__expf(sacc[nf][1] - nm0));
            float p2 = rna_tf32(__expf(sacc[nf][2] - nm1));
            float p3 = rna_tf32(__expf(sacc[nf][3] - nm1));
            ls0 += p0 + p1; ls1 += p2 + p3;
            int cbase = nf * 8 + 2 * t4;
            Ps[(qw + g) * AS + cbase]     = p0;
            Ps[(qw + g) * AS + cbase + 1] = p1;
            Ps[(qw + g + 8) * AS + cbase]     = p2;
            Ps[(qw + g + 8) * AS + cbase + 1] = p3;
        }
        ls0 += __shfl_xor_sync(0xffffffffu, ls0, 1);
        ls0 += __shfl_xor_sync(0xffffffffu, ls0, 2);
        ls1 += __shfl_xor_sync(0xffffffffu, ls1, 1);
        ls1 += __shfl_xor_sync(0xffffffffu, ls1, 2);
        l0 = l0 * sc0 + ls0;
        l1 = l1 * sc1 + ls1;
        m0 = nm0; m1 = nm1;

        // rescale O accumulators
#pragma unroll
        for (int nf = 0; nf < 8; nf++) {
            oacc[nf][0] *= sc0; oacc[nf][1] *= sc0;
            oacc[nf][2] *= sc1; oacc[nf][3] *= sc1;
        }
        __syncwarp();   // warp-private Ps region ready

        // O += P @ V : 8 dim-frags x 8 key-steps
#pragma unroll
        for (int kk = 0; kk < 64; kk += 8) {
            uint32_t af[4];
            af[0] = __float_as_uint(Ps[(qw + g) * AS + kk + t4]);
            af[1] = __float_as_uint(Ps[(qw + g + 8) * AS + kk + t4]);
            af[2] = __float_as_uint(Ps[(qw + g) * AS + kk + t4 + 4]);
            af[3] = __float_as_uint(Ps[(qw + g + 8) * AS + kk + t4 + 4]);
#pragma unroll
            for (int nf = 0; nf < 8; nf++) {
                uint32_t bf[2];
                bf[0] = __float_as_uint(VsT[(nf * 8 + g) * AS + kk + t4]);
                bf[1] = __float_as_uint(VsT[(nf * 8 + g) * AS + kk + t4 + 4]);
                mma_tf32(oacc[nf], af, bf);
            }
        }
    }

    // write out: rows qw+g and qw+g+8, dims nf*8 + 2*t4 (+1)
    float inv0 = 1.0f / l0, inv1 = 1.0f / l1;
    int ra = q0 + qw + g, rb = q0 + qw + g + 8;
    if (qw + g < nq) {
        float* op = out + (size_t)(base + ra) * D_ + h * 64;
#pragma unroll
        for (int nf = 0; nf < 8; nf++) {
            int cc = nf * 8 + 2 * t4;
            *(float2*)(op + cc) = make_float2(rna_tf32(oacc[nf][0] * inv0),
                                              rna_tf32(oacc[nf][1] * inv0));
        }
    }
    if (qw + g + 8 < nq) {
        float* op = out + (size_t)(base + rb) * D_ + h * 64;
#pragma unroll
        for (int nf = 0; nf < 8; nf++) {
            int cc = nf * 8 + 2 * t4;
            *(float2*)(op + cc) = make_float2(rna_tf32(oacc[nf][2] * inv1),
                                              rna_tf32(oacc[nf][3] * inv1));
        }
    }
}

// ---------------- host launch ----------------
extern "C" void kernel_launch(void* const* d_in, const int* in_sizes, int n_in,
                              void* d_out, int out_size) {
    const float* x     = (const float*)d_in[0];
    const int*   cu    = (const int*)  d_in[1];
    const float* g1    = (const float*)d_in[2];
    const float* beta1 = (const float*)d_in[3];
    const float* Wqkv  = (const float*)d_in[4];
    const float* bqkv  = (const float*)d_in[5];
    const float* Wo    = (const float*)d_in[6];
    const float* bo    = (const float*)d_in[7];
    const float* g2    = (const float*)d_in[8];
    const float* beta2 = (const float*)d_in[9];
    const float* W1    = (const float*)d_in[10];
    const float* b_fc1 = (const float*)d_in[11];
    const float* W2    = (const float*)d_in[12];
    const float* b_fc2 = (const float*)d_in[13];
    float* out = (float*)d_out;

    int total = in_sizes[0] / D_;   // 6144
    int nb    = in_sizes[1] - 1;    // 8

    float *xn, *qkv, *attn, *x2, *mid, *wqkvT, *woT, *w1T, *w2T;
    cudaGetSymbolAddress((void**)&xn,    g_xn);
    cudaGetSymbolAddress((void**)&qkv,   g_qkv);
    cudaGetSymbolAddress((void**)&attn,  g_attn);
    cudaGetSymbolAddress((void**)&x2,    g_x2);
    cudaGetSymbolAddress((void**)&mid,   g_mid);
    cudaGetSymbolAddress((void**)&wqkvT, g_WqkvT);
    cudaGetSymbolAddress((void**)&woT,   g_WoT);
    cudaGetSymbolAddress((void**)&w1T,   g_W1T);
    cudaGetSymbolAddress((void**)&w2T,   g_W2T);

    int mb = total / 128;
    dim3 tb(32, 8);

    const int ATTN_SMEM = 4 * 64 * AS * 4;   // 69632 B
    cudaFuncSetAttribute(attn_kernel, cudaFuncAttributeMaxDynamicSharedMemorySize, ATTN_SMEM);

    transpose_rna<<<dim3(3 * D_ / 32, D_ / 32), tb>>>(Wqkv, wqkvT, D_, 3 * D_);
    transpose_rna<<<dim3(D_ / 32, D_ / 32),     tb>>>(Wo,   woT,   D_, D_);
    transpose_rna<<<dim3(DFF_ / 32, D_ / 32),   tb>>>(W1,   w1T,   D_, DFF_);
    transpose_rna<<<dim3(D_ / 32, DFF_ / 32),   tb>>>(W2,   w2T,   DFF_, D_);

    ln_kernel<<<total, 256>>>(x, g1, beta1, xn);
    tgemm<0><<<dim3(3 * D_ / 128, mb), 128>>>(xn, wqkvT, bqkv, nullptr,
                                              qkv, total, 3 * D_, D_);
    attn_kernel<<<dim3(SMAX_ / 64, H_, nb), 128, ATTN_SMEM>>>(qkv, cu, attn);
    tgemm<1><<<dim3(D_ / 128, mb), 128>>>(attn, woT, bo, x, x2, total, D_, D_);
    ln_kernel<<<total, 256>>>(x2, g2, beta2, xn);
    tgemm<2><<<dim3(DFF_ / 128, mb), 128>>>(xn, w1T, b_fc1, nullptr,
                                            mid, total, DFF_, D_);
    tgemm<1><<<dim3(D_ / 128, mb), 128>>>(mid, w2T, b_fc2, x2,
                                          out, total, D_, DFF_);
}

// round 6
// speedup vs baseline: 1.1672x; 1.1672x over previous
#include <cuda_runtime.h>
#include <math.h>
#include <stdint.h>

#define D_    768
#define H_    12
#define HD_   64
#define DFF_  3072
#define MAXT  8192
#define SMAX_ 1024

// ---------------- scratch (no allocations allowed) ----------------
__device__ float g_xn  [(size_t)MAXT * D_];
__device__ float g_qkv [(size_t)MAXT * 3 * D_];
__device__ float g_attn[(size_t)MAXT * D_];
__device__ float g_x2  [(size_t)MAXT * D_];
__device__ float g_mid [(size_t)MAXT * DFF_];
__device__ float g_WqkvT[(size_t)3 * D_ * D_];
__device__ float g_WoT  [(size_t)D_ * D_];
__device__ float g_W1T  [(size_t)DFF_ * D_];
__device__ float g_W2T  [(size_t)D_ * DFF_];

// ---------------- helpers ----------------
__device__ __forceinline__ uint32_t smem_u32(const void* p) {
    uint32_t a;
    asm("{ .reg .u64 t; cvta.to.shared.u64 t, %1; cvt.u32.u64 %0, t; }" : "=r"(a) : "l"(p));
    return a;
}
__device__ __forceinline__ float rna_tf32(float x) {
    uint32_t u;
    asm("cvt.rna.tf32.f32 %0, %1;" : "=r"(u) : "f"(x));
    return __uint_as_float(u);
}
#define CP_ASYNC16(dst, src) \
    asm volatile("cp.async.cg.shared.global [%0], [%1], 16;" :: "r"(dst), "l"(src) : "memory")
#define CP_COMMIT() asm volatile("cp.async.commit_group;" ::: "memory")
#define CP_WAIT(n)  asm volatile("cp.async.wait_group %0;" :: "n"(n) : "memory")

__device__ __forceinline__ void mma_tf32(float* c, const uint32_t* a, const uint32_t* b) {
    asm volatile(
        "mma.sync.aligned.m16n8k8.row.col.f32.tf32.tf32.f32 "
        "{%0,%1,%2,%3}, {%4,%5,%6,%7}, {%8,%9}, {%0,%1,%2,%3};"
        : "+f"(c[0]), "+f"(c[1]), "+f"(c[2]), "+f"(c[3])
        : "r"(a[0]), "r"(a[1]), "r"(a[2]), "r"(a[3]), "r"(b[0]), "r"(b[1]));
}

// ---------------- transpose + tf32 round: WT[n][k] = rna(W[k][n]) ----------------
__global__ void __launch_bounds__(256) transpose_rna(const float* __restrict__ W,
                                                     float* __restrict__ WT,
                                                     int K, int N) {
    __shared__ float tile[32][33];
    int tx = threadIdx.x, ty = threadIdx.y;
    int n0 = blockIdx.x * 32, k0 = blockIdx.y * 32;
#pragma unroll
    for (int i = 0; i < 4; i++)
        tile[ty + 8 * i][tx] = W[(size_t)(k0 + ty + 8 * i) * N + n0 + tx];
    __syncthreads();
#pragma unroll
    for (int i = 0; i < 4; i++)
        WT[(size_t)(n0 + ty + 8 * i) * K + k0 + tx] = rna_tf32(tile[tx][ty + 8 * i]);
}

// ---------------- LayerNorm (tf32-rounded output) ----------------
__global__ void __launch_bounds__(256) ln_kernel(const float* __restrict__ x,
                                                 const float* __restrict__ g,
                                                 const float* __restrict__ be,
                                                 float* __restrict__ y) {
    int t = blockIdx.x;
    const float* xr = x + (size_t)t * D_;
    float*       yr = y + (size_t)t * D_;
    int tid = threadIdx.x;
    float v0 = xr[tid], v1 = xr[tid + 256], v2 = xr[tid + 512];
    float s  = v0 + v1 + v2;
    float s2 = v0 * v0 + v1 * v1 + v2 * v2;
    __shared__ float sh1[256], sh2[256];
    sh1[tid] = s; sh2[tid] = s2;
    __syncthreads();
    for (int o = 128; o > 0; o >>= 1) {
        if (tid < o) { sh1[tid] += sh1[tid + o]; sh2[tid] += sh2[tid + o]; }
        __syncthreads();
    }
    float mu  = sh1[0] * (1.0f / D_);
    float var = sh2[0] * (1.0f / D_) - mu * mu;
    float r   = rsqrtf(var + 1e-6f);
    yr[tid]       = rna_tf32((v0 - mu) * r * g[tid]       + be[tid]);
    yr[tid + 256] = rna_tf32((v1 - mu) * r * g[tid + 256] + be[tid + 256]);
    yr[tid + 512] = rna_tf32((v2 - mu) * r * g[tid + 512] + be[tid + 512]);
}

// ---------------- tf32 mma.sync GEMM: C[M,N] = A[M,K] @ BT[N,K]^T + epi ----------
// CTA 128x128, 128 threads, 4 warps (2x2), warp tile 64x64.
// K-chunk 32, 3-stage cp.async ring, ONE syncthreads per chunk.
// Row stride 36 floats: cp.async 16B-aligned, fragment LDS conflict-free.
#define TS 36
#define STG_F (128 * TS)
template <int EPI>
__global__ void __launch_bounds__(128) tgemm(const float* __restrict__ A,
                                             const float* __restrict__ BT,
                                             const float* __restrict__ bias,
                                             const float* __restrict__ res,
                                             float* __restrict__ C,
                                             int M, int N, int K) {
    extern __shared__ float sm[];
    float* As = sm;                 // [3][128*TS]
    float* Bs = sm + 3 * STG_F;     // [3][128*TS]

    int tid = threadIdx.x;
    int lane = tid & 31, wid = tid >> 5;
    int warpM = wid >> 1, warpN = wid & 1;
    int g = lane >> 2, t4 = lane & 3;
    int bm = blockIdx.y * 128, bn = blockIdx.x * 128;

    const float* gA = A  + (size_t)bm * K;
    const float* gB = BT + (size_t)bn * K;

    int lrow = tid >> 3;            // 0..15 (+16i)
    int lc4  = tid & 7;             // float4 index within 32-float chunk row

    float acc[4][8][4];
#pragma unroll
    for (int mf = 0; mf < 4; mf++)
#pragma unroll
        for (int nf = 0; nf < 8; nf++)
#pragma unroll
            for (int r = 0; r < 4; r++) acc[mf][nf][r] = 0.f;

    uint32_t sA0 = smem_u32(As), sB0 = smem_u32(Bs);
    int nc = K >> 5;

    // issue loads for chunk c into stage s
    auto issue = [&](int c, int s) {
        uint32_t sa = sA0 + (uint32_t)s * STG_F * 4;
        uint32_t sb = sB0 + (uint32_t)s * STG_F * 4;
        const float* a0 = gA + (c << 5) + lc4 * 4;
        const float* b0 = gB + (c << 5) + lc4 * 4;
#pragma unroll
        for (int i = 0; i < 8; i++) {
            int row = lrow + 16 * i;
            uint32_t off = (uint32_t)(row * TS + lc4 * 4) * 4;
            CP_ASYNC16(sa + off, a0 + (size_t)row * K);
            CP_ASYNC16(sb + off, b0 + (size_t)row * K);
        }
        CP_COMMIT();
    };

    issue(0, 0);
    if (nc > 1) issue(1, 1);

    for (int c = 0; c < nc; c++) {
        if (c + 1 < nc) { CP_WAIT(1); } else { CP_WAIT(0); }
        __syncthreads();                 // all threads done with stage (c+2)%3's last read
        if (c + 2 < nc) issue(c + 2, (c + 2) % 3);

        const float* as = As + (c % 3) * STG_F;
        const float* bs = Bs + (c % 3) * STG_F;
#pragma unroll
        for (int ko = 0; ko < 32; ko += 8) {
            uint32_t af[4][4];
#pragma unroll
            for (int mf = 0; mf < 4; mf++) {
                int r = warpM * 64 + mf * 16 + g;
                af[mf][0] = __float_as_uint(as[r * TS + ko + t4]);
                af[mf][1] = __float_as_uint(as[(r + 8) * TS + ko + t4]);
                af[mf][2] = __float_as_uint(as[r * TS + ko + t4 + 4]);
                af[mf][3] = __float_as_uint(as[(r + 8) * TS + ko + t4 + 4]);
            }
            uint32_t bf[8][2];
#pragma unroll
            for (int nf = 0; nf < 8; nf++) {
                int n = warpN * 64 + nf * 8 + g;
                bf[nf][0] = __float_as_uint(bs[n * TS + ko + t4]);
                bf[nf][1] = __float_as_uint(bs[n * TS + ko + t4 + 4]);
            }
#pragma unroll
            for (int mf = 0; mf < 4; mf++)
#pragma unroll
                for (int nf = 0; nf < 8; nf++)
                    mma_tf32(acc[mf][nf], af[mf], bf[nf]);
        }
    }

    // epilogue
#pragma unroll
    for (int mf = 0; mf < 4; mf++) {
        int r0 = bm + warpM * 64 + mf * 16 + g;
#pragma unroll
        for (int nf = 0; nf < 8; nf++) {
            int cc = bn + warpN * 64 + nf * 8 + t4 * 2;
            float b0 = bias[cc], b1 = bias[cc + 1];
            float v00 = acc[mf][nf][0] + b0, v01 = acc[mf][nf][1] + b1;
            float v10 = acc[mf][nf][2] + b0, v11 = acc[mf][nf][3] + b1;
            if (EPI == 1) {
                const float* rp0 = res + (size_t)r0 * N + cc;
                const float* rp1 = res + (size_t)(r0 + 8) * N + cc;
                v00 += rp0[0]; v01 += rp0[1];
                v10 += rp1[0]; v11 += rp1[1];
            }
            if (EPI == 2) {
                v00 = rna_tf32(0.5f * v00 * (1.0f + erff(v00 * 0.70710678118654752f)));
                v01 = rna_tf32(0.5f * v01 * (1.0f + erff(v01 * 0.70710678118654752f)));
                v10 = rna_tf32(0.5f * v10 * (1.0f + erff(v10 * 0.70710678118654752f)));
                v11 = rna_tf32(0.5f * v11 * (1.0f + erff(v11 * 0.70710678118654752f)));
            }
            *(float2*)(C + (size_t)r0 * N + cc)       = make_float2(v00, v01);
            *(float2*)(C + (size_t)(r0 + 8) * N + cc) = make_float2(v10, v11);
        }
    }
}

// ---------------- Ragged flash attention (R4 FFMA version — proven) --------------
__global__ void __launch_bounds__(256) attn_kernel(const float* __restrict__ qkv,
                                                   const int* __restrict__ cu,
                                                   float* __restrict__ out) {
    int qt = blockIdx.x, h = blockIdx.y, b = blockIdx.z;
    int base = cu[b];
    int len  = cu[b + 1] - base;
    int q0   = qt * 32;
    if (q0 >= len) return;
    int nq = min(32, len - q0);

    __shared__ float Qs[32][68];
    __shared__ float KsT[64][68];
    __shared__ float Vs[64][68];
    __shared__ float Ps[32][68];

    int tid = threadIdx.x;
    for (int idx = tid; idx < 32 * 64; idx += 256) {
        int qi = idx >> 6, d = idx & 63;
        Qs[qi][d] = (qi < nq)
            ? qkv[(size_t)(base + q0 + qi) * 2304 + h * 64 + d] * 0.125f
            : 0.f;
    }

    int qg = tid >> 4;
    int kx = tid & 15;
    int qa = qg * 2, qb = qg * 2 + 1;

    float m0 = -1e30f, m1 = -1e30f, l0 = 0.f, l1 = 0.f;
    float o0[4] = {0.f, 0.f, 0.f, 0.f}, o1[4] = {0.f, 0.f, 0.f, 0.f};

    for (int k0 = 0; k0 < len; k0 += 64) {
        int nk = min(64, len - k0);
        __syncthreads();
        for (int idx = tid; idx < 64 * 64; idx += 256) {
            int j = idx >> 6, d = idx & 63;
            float kv = 0.f, vv = 0.f;
            if (j < nk) {
                size_t r = (size_t)(base + k0 + j) * 2304 + h * 64 + d;
                kv = qkv[r + 768];
                vv = qkv[r + 1536];
            }
            KsT[d][j] = kv;
            Vs[j][d]  = vv;
        }
        __syncthreads();

        float s[2][4];
#pragma unroll
        for (int cc = 0; cc < 4; cc++) { s[0][cc] = 0.f; s[1][cc] = 0.f; }
#pragma unroll
        for (int d = 0; d < 64; d++) {
            float qv0 = Qs[qa][d];
            float qv1 = Qs[qb][d];
            float4 kq = *(const float4*)&KsT[d][kx * 4];
            s[0][0] += qv0 * kq.x; s[0][1] += qv0 * kq.y;
            s[0][2] += qv0 * kq.z; s[0][3] += qv0 * kq.w;
            s[1][0] += qv1 * kq.x; s[1][1] += qv1 * kq.y;
            s[1][2] += qv1 * kq.z; s[1][3] += qv1 * kq.w;
        }
#pragma unroll
        for (int cc = 0; cc < 4; cc++) {
            if (kx * 4 + cc >= nk) { s[0][cc] = -1e30f; s[1][cc] = -1e30f; }
        }

        float tm0 = fmaxf(fmaxf(s[0][0], s[0][1]), fmaxf(s[0][2], s[0][3]));
        float tm1 = fmaxf(fmaxf(s[1][0], s[1][1]), fmaxf(s[1][2], s[1][3]));
#pragma unroll
        for (int off = 8; off >= 1; off >>= 1) {
            tm0 = fmaxf(tm0, __shfl_xor_sync(0xffffffffu, tm0, off));
            tm1 = fmaxf(tm1, __shfl_xor_sync(0xffffffffu, tm1, off));
        }
        float nm0 = fmaxf(m0, tm0), nm1 = fmaxf(m1, tm1);
        float sc0 = __expf(m0 - nm0), sc1 = __expf(m1 - nm1);

        float p0[4], p1[4];
        float ls0 = 0.f, ls1 = 0.f;
#pragma unroll
        for (int cc = 0; cc < 4; cc++) {
            p0[cc] = __expf(s[0][cc] - nm0);
            p1[cc] = __expf(s[1][cc] - nm1);
            ls0 += p0[cc]; ls1 += p1[cc];
        }
        *(float4*)&Ps[qa][kx * 4] = *(float4*)p0;
        *(float4*)&Ps[qb][kx * 4] = *(float4*)p1;
#pragma unroll
        for (int off = 8; off >= 1; off >>= 1) {
            ls0 += __shfl_xor_sync(0xffffffffu, ls0, off);
            ls1 += __shfl_xor_sync(0xffffffffu, ls1, off);
        }
        l0 = l0 * sc0 + ls0;
        l1 = l1 * sc1 + ls1;
        m0 = nm0; m1 = nm1;

#pragma unroll
        for (int dd = 0; dd < 4; dd++) { o0[dd] *= sc0; o1[dd] *= sc1; }

        __syncthreads();

#pragma unroll 8
        for (int j = 0; j < 64; j++) {
            float pj0 = Ps[qa][j];
            float pj1 = Ps[qb][j];
            float4 vv = *(const float4*)&Vs[j][kx * 4];
            o0[0] += pj0 * vv.x; o0[1] += pj0 * vv.y;
            o0[2] += pj0 * vv.z; o0[3] += pj0 * vv.w;
            o1[0] += pj1 * vv.x; o1[1] += pj1 * vv.y;
            o1[2] += pj1 * vv.z; o1[3] += pj1 * vv.w;
        }
    }

    float inv0 = 1.0f / l0, inv1 = 1.0f / l1;
    if (qa < nq) {
        float w[4];
#pragma unroll
        for (int dd = 0; dd < 4; dd++) w[dd] = rna_tf32(o0[dd] * inv0);
        *(float4*)&out[(size_t)(base + q0 + qa) * D_ + h * 64 + kx * 4] = *(float4*)w;
    }
    if (qb < nq) {
        float w[4];
#pragma unroll
        for (int dd = 0; dd < 4; dd++) w[dd] = rna_tf32(o1[dd] * inv1);
        *(float4*)&out[(size_t)(base + q0 + qb) * D_ + h * 64 + kx * 4] = *(float4*)w;
    }
}

// ---------------- host launch ----------------
extern "C" void kernel_launch(void* const* d_in, const int* in_sizes, int n_in,
                              void* d_out, int out_size) {
    const float* x     = (const float*)d_in[0];
    const int*   cu    = (const int*)  d_in[1];
    const float* g1    = (const float*)d_in[2];
    const float* beta1 = (const float*)d_in[3];
    const float* Wqkv  = (const float*)d_in[4];
    const float* bqkv  = (const float*)d_in[5];
    const float* Wo    = (const float*)d_in[6];
    const float* bo    = (const float*)d_in[7];
    const float* g2    = (const float*)d_in[8];
    const float* beta2 = (const float*)d_in[9];
    const float* W1    = (const float*)d_in[10];
    const float* b_fc1 = (const float*)d_in[11];
    const float* W2    = (const float*)d_in[12];
    const float* b_fc2 = (const float*)d_in[13];
    float* out = (float*)d_out;

    int total = in_sizes[0] / D_;   // 6144
    int nb    = in_sizes[1] - 1;    // 8

    float *xn, *qkv, *attn, *x2, *mid, *wqkvT, *woT, *w1T, *w2T;
    cudaGetSymbolAddress((void**)&xn,    g_xn);
    cudaGetSymbolAddress((void**)&qkv,   g_qkv);
    cudaGetSymbolAddress((void**)&attn,  g_attn);
    cudaGetSymbolAddress((void**)&x2,    g_x2);
    cudaGetSymbolAddress((void**)&mid,   g_mid);
    cudaGetSymbolAddress((void**)&wqkvT, g_WqkvT);
    cudaGetSymbolAddress((void**)&woT,   g_WoT);
    cudaGetSymbolAddress((void**)&w1T,   g_W1T);
    cudaGetSymbolAddress((void**)&w2T,   g_W2T);

    int mb = total / 128;
    dim3 tb(32, 8);

    const int GEMM_SMEM = 2 * 3 * STG_F * 4;   // 110592 B
    cudaFuncSetAttribute(tgemm<0>, cudaFuncAttributeMaxDynamicSharedMemorySize, GEMM_SMEM);
    cudaFuncSetAttribute(tgemm<1>, cudaFuncAttributeMaxDynamicSharedMemorySize, GEMM_SMEM);
    cudaFuncSetAttribute(tgemm<2>, cudaFuncAttributeMaxDynamicSharedMemorySize, GEMM_SMEM);

    transpose_rna<<<dim3(3 * D_ / 32, D_ / 32), tb>>>(Wqkv, wqkvT, D_, 3 * D_);
    transpose_rna<<<dim3(D_ / 32, D_ / 32),     tb>>>(Wo,   woT,   D_, D_);
    transpose_rna<<<dim3(DFF_ / 32, D_ / 32),   tb>>>(W1,   w1T,   D_, DFF_);
    transpose_rna<<<dim3(D_ / 32, DFF_ / 32),   tb>>>(W2,   w2T,   DFF_, D_);

    ln_kernel<<<total, 256>>>(x, g1, beta1, xn);
    tgemm<0><<<dim3(3 * D_ / 128, mb), 128, GEMM_SMEM>>>(xn, wqkvT, bqkv, nullptr,
                                                         qkv, total, 3 * D_, D_);
    attn_kernel<<<dim3(SMAX_ / 32, H_, nb), 256>>>(qkv, cu, attn);
    tgemm<1><<<dim3(D_ / 128, mb), 128, GEMM_SMEM>>>(attn, woT, bo, x, x2,
                                                     total, D_, D_);
    ln_kernel<<<total, 256>>>(x2, g2, beta2, xn);
    tgemm<2><<<dim3(DFF_ / 128, mb), 128, GEMM_SMEM>>>(xn, w1T, b_fc1, nullptr,
                                                       mid, total, DFF_, D_);
    tgemm<1><<<dim3(D_ / 128, mb), 128, GEMM_SMEM>>>(mid, w2T, b_fc2, x2,
                                                     out, total, D_, DFF_);
}

// round 7
// speedup vs baseline: 1.4271x; 1.2227x over previous
#include <cuda_runtime.h>
#include <cuda_fp16.h>
#include <math.h>
#include <stdint.h>

#define D_    768
#define H_    12
#define HD_   64
#define DFF_  3072
#define MAXT  8192
#define SMAX_ 1024

// ---------------- scratch (no allocations allowed) ----------------
__device__ __half g_xnh  [(size_t)MAXT * D_];      // LN output (half)
__device__ float  g_qkv  [(size_t)MAXT * 3 * D_];  // qkv (fp32 for attention)
__device__ __half g_attnh[(size_t)MAXT * D_];      // attention output (half)
__device__ float  g_x2   [(size_t)MAXT * D_];      // residual after attention (fp32)
__device__ __half g_midh [(size_t)MAXT * DFF_];    // FFN hidden (half)
__device__ __half g_WqkvTh[(size_t)3 * D_ * D_];
__device__ __half g_WoTh  [(size_t)D_ * D_];
__device__ __half g_W1Th  [(size_t)DFF_ * D_];
__device__ __half g_W2Th  [(size_t)D_ * DFF_];

// ---------------- helpers ----------------
__device__ __forceinline__ uint32_t smem_u32(const void* p) {
    uint32_t a;
    asm("{ .reg .u64 t; cvta.to.shared.u64 t, %1; cvt.u32.u64 %0, t; }" : "=r"(a) : "l"(p));
    return a;
}
__device__ __forceinline__ float rna_tf32(float x) {
    uint32_t u;
    asm("cvt.rna.tf32.f32 %0, %1;" : "=r"(u) : "f"(x));
    return __uint_as_float(u);
}
#define CP_ASYNC16(dst, src) \
    asm volatile("cp.async.cg.shared.global [%0], [%1], 16;" :: "r"(dst), "l"(src) : "memory")
#define CP_COMMIT() asm volatile("cp.async.commit_group;" ::: "memory")
#define CP_WAIT(n)  asm volatile("cp.async.wait_group %0;" :: "n"(n) : "memory")

__device__ __forceinline__ void mma_f16(float* c, const uint32_t* a, const uint32_t* b) {
    asm volatile(
        "mma.sync.aligned.m16n8k16.row.col.f32.f16.f16.f32 "
        "{%0,%1,%2,%3}, {%4,%5,%6,%7}, {%8,%9}, {%0,%1,%2,%3};"
        : "+f"(c[0]), "+f"(c[1]), "+f"(c[2]), "+f"(c[3])
        : "r"(a[0]), "r"(a[1]), "r"(a[2]), "r"(a[3]), "r"(b[0]), "r"(b[1]));
}

// ---------------- transpose + fp16 round: WT[n][k] = (half)W[k][n] ----------------
__global__ void __launch_bounds__(256) transpose_h(const float* __restrict__ W,
                                                   __half* __restrict__ WT,
                                                   int K, int N) {
    __shared__ float tile[32][33];
    int tx = threadIdx.x, ty = threadIdx.y;
    int n0 = blockIdx.x * 32, k0 = blockIdx.y * 32;
#pragma unroll
    for (int i = 0; i < 4; i++)
        tile[ty + 8 * i][tx] = W[(size_t)(k0 + ty + 8 * i) * N + n0 + tx];
    __syncthreads();
#pragma unroll
    for (int i = 0; i < 4; i++)
        WT[(size_t)(n0 + ty + 8 * i) * K + k0 + tx] = __float2half(tile[tx][ty + 8 * i]);
}

// ---------------- LayerNorm (fp16 output) ----------------
__global__ void __launch_bounds__(256) ln_kernel(const float* __restrict__ x,
                                                 const float* __restrict__ g,
                                                 const float* __restrict__ be,
                                                 __half* __restrict__ y) {
    int t = blockIdx.x;
    const float* xr = x + (size_t)t * D_;
    __half*      yr = y + (size_t)t * D_;
    int tid = threadIdx.x;
    float v0 = xr[tid], v1 = xr[tid + 256], v2 = xr[tid + 512];
    float s  = v0 + v1 + v2;
    float s2 = v0 * v0 + v1 * v1 + v2 * v2;
    __shared__ float sh1[256], sh2[256];
    sh1[tid] = s; sh2[tid] = s2;
    __syncthreads();
    for (int o = 128; o > 0; o >>= 1) {
        if (tid < o) { sh1[tid] += sh1[tid + o]; sh2[tid] += sh2[tid + o]; }
        __syncthreads();
    }
    float mu  = sh1[0] * (1.0f / D_);
    float var = sh2[0] * (1.0f / D_) - mu * mu;
    float r   = rsqrtf(var + 1e-6f);
    yr[tid]       = __float2half((v0 - mu) * r * g[tid]       + be[tid]);
    yr[tid + 256] = __float2half((v1 - mu) * r * g[tid + 256] + be[tid + 256]);
    yr[tid + 512] = __float2half((v2 - mu) * r * g[tid + 512] + be[tid + 512]);
}

// ---------------- fp16 mma.sync GEMM: C[M,N] = A[M,K] @ BT[N,K]^T + epi ----------
// CTA 128x128, 128 threads, 4 warps (2x2), warp tile 64x64.
// K-chunk 32 halves, 3-stage cp.async ring, one syncthreads per chunk.
// Row stride 40 halves (80B): cp.async 16B-aligned, conflict-free half2 frag LDS.
#define TSH   40
#define STG_H (128 * TSH)                  // halves per stage per matrix
template <int EPI, typename OutT>
__global__ void __launch_bounds__(128) tgemm(const __half* __restrict__ A,
                                             const __half* __restrict__ BT,
                                             const float* __restrict__ bias,
                                             const float* __restrict__ res,
                                             OutT* __restrict__ C,
                                             int M, int N, int K) {
    extern __shared__ __half smh[];
    __half* As = smh;                      // [3][STG_H]
    __half* Bs = smh + 3 * STG_H;          // [3][STG_H]

    int tid = threadIdx.x;
    int lane = tid & 31, wid = tid >> 5;
    int warpM = wid >> 1, warpN = wid & 1;
    int g = lane >> 2, t4 = lane & 3;
    int bm = blockIdx.y * 128, bn = blockIdx.x * 128;

    const __half* gA = A  + (size_t)bm * K;
    const __half* gB = BT + (size_t)bn * K;

    int lrow = tid >> 2;                   // 0..31 (+32i)
    int c8   = tid & 3;                    // 8-half group within 32-half chunk row

    float acc[4][8][4];
#pragma unroll
    for (int mf = 0; mf < 4; mf++)
#pragma unroll
        for (int nf = 0; nf < 8; nf++)
#pragma unroll
            for (int r = 0; r < 4; r++) acc[mf][nf][r] = 0.f;

    uint32_t sA0 = smem_u32(As), sB0 = smem_u32(Bs);
    int nc = K >> 5;

    auto issue = [&](int c, int s) {
        uint32_t sa = sA0 + (uint32_t)s * STG_H * 2;
        uint32_t sb = sB0 + (uint32_t)s * STG_H * 2;
        const __half* a0 = gA + (c << 5) + c8 * 8;
        const __half* b0 = gB + (c << 5) + c8 * 8;
#pragma unroll
        for (int i = 0; i < 4; i++) {
            int row = lrow + 32 * i;
            uint32_t off = (uint32_t)(row * TSH + c8 * 8) * 2;
            CP_ASYNC16(sa + off, a0 + (size_t)row * K);
            CP_ASYNC16(sb + off, b0 + (size_t)row * K);
        }
        CP_COMMIT();
    };

    issue(0, 0);
    if (nc > 1) issue(1, 1);

    for (int c = 0; c < nc; c++) {
        if (c + 1 < nc) { CP_WAIT(1); } else { CP_WAIT(0); }
        __syncthreads();
        if (c + 2 < nc) issue(c + 2, (c + 2) % 3);

        const __half* as = As + (c % 3) * STG_H;
        const __half* bs = Bs + (c % 3) * STG_H;
#pragma unroll
        for (int ko = 0; ko < 32; ko += 16) {
            uint32_t af[4][4];
#pragma unroll
            for (int mf = 0; mf < 4; mf++) {
                int r = warpM * 64 + mf * 16 + g;
                af[mf][0] = *(const uint32_t*)&as[r * TSH + ko + 2 * t4];
                af[mf][1] = *(const uint32_t*)&as[(r + 8) * TSH + ko + 2 * t4];
                af[mf][2] = *(const uint32_t*)&as[r * TSH + ko + 2 * t4 + 8];
                af[mf][3] = *(const uint32_t*)&as[(r + 8) * TSH + ko + 2 * t4 + 8];
            }
            uint32_t bf[8][2];
#pragma unroll
            for (int nf = 0; nf < 8; nf++) {
                int n = warpN * 64 + nf * 8 + g;
                bf[nf][0] = *(const uint32_t*)&bs[n * TSH + ko + 2 * t4];
                bf[nf][1] = *(const uint32_t*)&bs[n * TSH + ko + 2 * t4 + 8];
            }
#pragma unroll
            for (int mf = 0; mf < 4; mf++)
#pragma unroll
                for (int nf = 0; nf < 8; nf++)
                    mma_f16(acc[mf][nf], af[mf], bf[nf]);
        }
    }

    // epilogue
#pragma unroll
    for (int mf = 0; mf < 4; mf++) {
        int r0 = bm + warpM * 64 + mf * 16 + g;
#pragma unroll
        for (int nf = 0; nf < 8; nf++) {
            int cc = bn + warpN * 64 + nf * 8 + t4 * 2;
            float b0 = bias[cc], b1 = bias[cc + 1];
            float v00 = acc[mf][nf][0] + b0, v01 = acc[mf][nf][1] + b1;
            float v10 = acc[mf][nf][2] + b0, v11 = acc[mf][nf][3] + b1;
            if (EPI == 1) {
                const float* rp0 = res + (size_t)r0 * N + cc;
                const float* rp1 = res + (size_t)(r0 + 8) * N + cc;
                v00 += rp0[0]; v01 += rp0[1];
                v10 += rp1[0]; v11 += rp1[1];
            }
            if (EPI == 2) {
                v00 = 0.5f * v00 * (1.0f + erff(v00 * 0.70710678118654752f));
                v01 = 0.5f * v01 * (1.0f + erff(v01 * 0.70710678118654752f));
                v10 = 0.5f * v10 * (1.0f + erff(v10 * 0.70710678118654752f));
                v11 = 0.5f * v11 * (1.0f + erff(v11 * 0.70710678118654752f));
            }
            if (sizeof(OutT) == 2) {
                __half2 h0 = __floats2half2_rn(v00, v01);
                __half2 h1 = __floats2half2_rn(v10, v11);
                *(__half2*)((__half*)C + (size_t)r0 * N + cc)       = h0;
                *(__half2*)((__half*)C + (size_t)(r0 + 8) * N + cc) = h1;
            } else {
                *(float2*)((float*)C + (size_t)r0 * N + cc)       = make_float2(v00, v01);
                *(float2*)((float*)C + (size_t)(r0 + 8) * N + cc) = make_float2(v10, v11);
            }
        }
    }
}

// ---------------- Ragged flash attention (fp32 math; fp16 output) ----------------
__global__ void __launch_bounds__(256) attn_kernel(const float* __restrict__ qkv,
                                                   const int* __restrict__ cu,
                                                   __half* __restrict__ out) {
    int qt = blockIdx.x, h = blockIdx.y, b = blockIdx.z;
    int base = cu[b];
    int len  = cu[b + 1] - base;
    int q0   = qt * 32;
    if (q0 >= len) return;
    int nq = min(32, len - q0);

    __shared__ float Qs[32][68];
    __shared__ float KsT[64][68];
    __shared__ float Vs[64][68];
    __shared__ float Ps[32][68];

    int tid = threadIdx.x;
    for (int idx = tid; idx < 32 * 64; idx += 256) {
        int qi = idx >> 6, d = idx & 63;
        Qs[qi][d] = (qi < nq)
            ? qkv[(size_t)(base + q0 + qi) * 2304 + h * 64 + d] * 0.125f
            : 0.f;
    }

    int qg = tid >> 4;
    int kx = tid & 15;
    int qa = qg * 2, qb = qg * 2 + 1;

    float m0 = -1e30f, m1 = -1e30f, l0 = 0.f, l1 = 0.f;
    float o0[4] = {0.f, 0.f, 0.f, 0.f}, o1[4] = {0.f, 0.f, 0.f, 0.f};

    for (int k0 = 0; k0 < len; k0 += 64) {
        int nk = min(64, len - k0);
        __syncthreads();
        for (int idx = tid; idx < 64 * 64; idx += 256) {
            int j = idx >> 6, d = idx & 63;
            float kv = 0.f, vv = 0.f;
            if (j < nk) {
                size_t r = (size_t)(base + k0 + j) * 2304 + h * 64 + d;
                kv = qkv[r + 768];
                vv = qkv[r + 1536];
            }
            KsT[d][j] = kv;
            Vs[j][d]  = vv;
        }
        __syncthreads();

        float s[2][4];
#pragma unroll
        for (int cc = 0; cc < 4; cc++) { s[0][cc] = 0.f; s[1][cc] = 0.f; }
#pragma unroll
        for (int d = 0; d < 64; d++) {
            float qv0 = Qs[qa][d];
            float qv1 = Qs[qb][d];
            float4 kq = *(const float4*)&KsT[d][kx * 4];
            s[0][0] += qv0 * kq.x; s[0][1] += qv0 * kq.y;
            s[0][2] += qv0 * kq.z; s[0][3] += qv0 * kq.w;
            s[1][0] += qv1 * kq.x; s[1][1] += qv1 * kq.y;
            s[1][2] += qv1 * kq.z; s[1][3] += qv1 * kq.w;
        }
#pragma unroll
        for (int cc = 0; cc < 4; cc++) {
            if (kx * 4 + cc >= nk) { s[0][cc] = -1e30f; s[1][cc] = -1e30f; }
        }

        float tm0 = fmaxf(fmaxf(s[0][0], s[0][1]), fmaxf(s[0][2], s[0][3]));
        float tm1 = fmaxf(fmaxf(s[1][0], s[1][1]), fmaxf(s[1][2], s[1][3]));
#pragma unroll
        for (int off = 8; off >= 1; off >>= 1) {
            tm0 = fmaxf(tm0, __shfl_xor_sync(0xffffffffu, tm0, off));
            tm1 = fmaxf(tm1, __shfl_xor_sync(0xffffffffu, tm1, off));
        }
        float nm0 = fmaxf(m0, tm0), nm1 = fmaxf(m1, tm1);
        float sc0 = __expf(m0 - nm0), sc1 = __expf(m1 - nm1);

        float p0[4], p1[4];
        float ls0 = 0.f, ls1 = 0.f;
#pragma unroll
        for (int cc = 0; cc < 4; cc++) {
            p0[cc] = __expf(s[0][cc] - nm0);
            p1[cc] = __expf(s[1][cc] - nm1);
            ls0 += p0[cc]; ls1 += p1[cc];
        }
        *(float4*)&Ps[qa][kx * 4] = *(float4*)p0;
        *(float4*)&Ps[qb][kx * 4] = *(float4*)p1;
#pragma unroll
        for (int off = 8; off >= 1; off >>= 1) {
            ls0 += __shfl_xor_sync(0xffffffffu, ls0, off);
            ls1 += __shfl_xor_sync(0xffffffffu, ls1, off);
        }
        l0 = l0 * sc0 + ls0;
        l1 = l1 * sc1 + ls1;
        m0 = nm0; m1 = nm1;

#pragma unroll
        for (int dd = 0; dd < 4; dd++) { o0[dd] *= sc0; o1[dd] *= sc1; }

        __syncthreads();

#pragma unroll 8
        for (int j = 0; j < 64; j++) {
            float pj0 = Ps[qa][j];
            float pj1 = Ps[qb][j];
            float4 vv = *(const float4*)&Vs[j][kx * 4];
            o0[0] += pj0 * vv.x; o0[1] += pj0 * vv.y;
            o0[2] += pj0 * vv.z; o0[3] += pj0 * vv.w;
            o1[0] += pj1 * vv.x; o1[1] += pj1 * vv.y;
            o1[2] += pj1 * vv.z; o1[3] += pj1 * vv.w;
        }
    }

    float inv0 = 1.0f / l0, inv1 = 1.0f / l1;
    if (qa < nq) {
        __half2 h0 = __floats2half2_rn(o0[0] * inv0, o0[1] * inv0);
        __half2 h1 = __floats2half2_rn(o0[2] * inv0, o0[3] * inv0);
        uint2 pk = make_uint2(*(uint32_t*)&h0, *(uint32_t*)&h1);
        *(uint2*)&out[(size_t)(base + q0 + qa) * D_ + h * 64 + kx * 4] = pk;
    }
    if (qb < nq) {
        __half2 h0 = __floats2half2_rn(o1[0] * inv1, o1[1] * inv1);
        __half2 h1 = __floats2half2_rn(o1[2] * inv1, o1[3] * inv1);
        uint2 pk = make_uint2(*(uint32_t*)&h0, *(uint32_t*)&h1);
        *(uint2*)&out[(size_t)(base + q0 + qb) * D_ + h * 64 + kx * 4] = pk;
    }
}

// ---------------- host launch ----------------
extern "C" void kernel_launch(void* const* d_in, const int* in_sizes, int n_in,
                              void* d_out, int out_size) {
    const float* x     = (const float*)d_in[0];
    const int*   cu    = (const int*)  d_in[1];
    const float* g1    = (const float*)d_in[2];
    const float* beta1 = (const float*)d_in[3];
    const float* Wqkv  = (const float*)d_in[4];
    const float* bqkv  = (const float*)d_in[5];
    const float* Wo    = (const float*)d_in[6];
    const float* bo    = (const float*)d_in[7];
    const float* g2    = (const float*)d_in[8];
    const float* beta2 = (const float*)d_in[9];
    const float* W1    = (const float*)d_in[10];
    const float* b_fc1 = (const float*)d_in[11];
    const float* W2    = (const float*)d_in[12];
    const float* b_fc2 = (const float*)d_in[13];
    float* out = (float*)d_out;

    int total = in_sizes[0] / D_;   // 6144
    int nb    = in_sizes[1] - 1;    // 8

    __half *xnh, *attnh, *midh, *wqkvTh, *woTh, *w1Th, *w2Th;
    float  *qkv, *x2;
    cudaGetSymbolAddress((void**)&xnh,    g_xnh);
    cudaGetSymbolAddress((void**)&qkv,    g_qkv);
    cudaGetSymbolAddress((void**)&attnh,  g_attnh);
    cudaGetSymbolAddress((void**)&x2,     g_x2);
    cudaGetSymbolAddress((void**)&midh,   g_midh);
    cudaGetSymbolAddress((void**)&wqkvTh, g_WqkvTh);
    cudaGetSymbolAddress((void**)&woTh,   g_WoTh);
    cudaGetSymbolAddress((void**)&w1Th,   g_W1Th);
    cudaGetSymbolAddress((void**)&w2Th,   g_W2Th);

    int mb = total / 128;
    dim3 tb(32, 8);

    const int GEMM_SMEM = 2 * 3 * STG_H * 2;   // 61440 B
    cudaFuncSetAttribute((const void*)tgemm<0, float>,  cudaFuncAttributeMaxDynamicSharedMemorySize, GEMM_SMEM);
    cudaFuncSetAttribute((const void*)tgemm<1, float>,  cudaFuncAttributeMaxDynamicSharedMemorySize, GEMM_SMEM);
    cudaFuncSetAttribute((const void*)tgemm<2, __half>, cudaFuncAttributeMaxDynamicSharedMemorySize, GEMM_SMEM);

    transpose_h<<<dim3(3 * D_ / 32, D_ / 32), tb>>>(Wqkv, wqkvTh, D_, 3 * D_);
    transpose_h<<<dim3(D_ / 32, D_ / 32),     tb>>>(Wo,   woTh,   D_, D_);
    transpose_h<<<dim3(DFF_ / 32, D_ / 32),   tb>>>(W1,   w1Th,   D_, DFF_);
    transpose_h<<<dim3(D_ / 32, DFF_ / 32),   tb>>>(W2,   w2Th,   DFF_, D_);

    ln_kernel<<<total, 256>>>(x, g1, beta1, xnh);
    tgemm<0, float><<<dim3(3 * D_ / 128, mb), 128, GEMM_SMEM>>>(
        xnh, wqkvTh, bqkv, nullptr, qkv, total, 3 * D_, D_);
    attn_kernel<<<dim3(SMAX_ / 32, H_, nb), 256>>>(qkv, cu, attnh);
    tgemm<1, float><<<dim3(D_ / 128, mb), 128, GEMM_SMEM>>>(
        attnh, woTh, bo, x, x2, total, D_, D_);
    ln_kernel<<<total, 256>>>(x2, g2, beta2, xnh);
    tgemm<2, __half><<<dim3(DFF_ / 128, mb), 128, GEMM_SMEM>>>(
        xnh, w1Th, b_fc1, nullptr, midh, total, DFF_, D_);
    tgemm<1, float><<<dim3(D_ / 128, mb), 128, GEMM_SMEM>>>(
        midh, w2Th, b_fc2, x2, out, total, D_, DFF_);
}

// round 10
// speedup vs baseline: 2.6228x; 1.8378x over previous
#include <cuda_runtime.h>
#include <cuda_fp16.h>
#include <math.h>
#include <stdint.h>

#define D_    768
#define H_    12
#define HD_   64
#define DFF_  3072
#define MAXT  8192
#define SMAX_ 1024

// ---------------- scratch (no allocations allowed) ----------------
__device__ __half g_xnh  [(size_t)MAXT * D_];
__device__ __half g_qkvh [(size_t)MAXT * 3 * D_];
__device__ __half g_attnh[(size_t)MAXT * D_];
__device__ float  g_x2   [(size_t)MAXT * D_];
__device__ __half g_midh [(size_t)MAXT * DFF_];
__device__ __half g_WqkvTh[(size_t)3 * D_ * D_];
__device__ __half g_WoTh  [(size_t)D_ * D_];
__device__ __half g_W1Th  [(size_t)DFF_ * D_];
__device__ __half g_W2Th  [(size_t)D_ * DFF_];

// ---------------- helpers ----------------
__device__ __forceinline__ uint32_t smem_u32(const void* p) {
    uint32_t a;
    asm("{ .reg .u64 t; cvta.to.shared.u64 t, %1; cvt.u32.u64 %0, t; }" : "=r"(a) : "l"(p));
    return a;
}
#define CP_ASYNC16(dst, src) \
    asm volatile("cp.async.cg.shared.global [%0], [%1], 16;" :: "r"(dst), "l"(src) : "memory")
#define CP_COMMIT() asm volatile("cp.async.commit_group;" ::: "memory")
#define CP_WAIT(n)  asm volatile("cp.async.wait_group %0;" :: "n"(n) : "memory")

__device__ __forceinline__ void mma_f16(float* c, const uint32_t* a, const uint32_t* b) {
    asm volatile(
        "mma.sync.aligned.m16n8k16.row.col.f32.f16.f16.f32 "
        "{%0,%1,%2,%3}, {%4,%5,%6,%7}, {%8,%9}, {%0,%1,%2,%3};"
        : "+f"(c[0]), "+f"(c[1]), "+f"(c[2]), "+f"(c[3])
        : "r"(a[0]), "r"(a[1]), "r"(a[2]), "r"(a[3]), "r"(b[0]), "r"(b[1]));
}

// ---------------- transpose + fp16 round ----------------
__global__ void __launch_bounds__(256) transpose_h(const float* __restrict__ W,
                                                   __half* __restrict__ WT,
                                                   int K, int N) {
    __shared__ float tile[32][33];
    int tx = threadIdx.x, ty = threadIdx.y;
    int n0 = blockIdx.x * 32, k0 = blockIdx.y * 32;
#pragma unroll
    for (int i = 0; i < 4; i++)
        tile[ty + 8 * i][tx] = W[(size_t)(k0 + ty + 8 * i) * N + n0 + tx];
    __syncthreads();
#pragma unroll
    for (int i = 0; i < 4; i++)
        WT[(size_t)(n0 + ty + 8 * i) * K + k0 + tx] = __float2half(tile[tx][ty + 8 * i]);
}

// ---------------- LayerNorm (fp16 output) ----------------
__global__ void __launch_bounds__(256) ln_kernel(const float* __restrict__ x,
                                                 const float* __restrict__ g,
                                                 const float* __restrict__ be,
                                                 __half* __restrict__ y) {
    int t = blockIdx.x;
    const float* xr = x + (size_t)t * D_;
    __half*      yr = y + (size_t)t * D_;
    int tid = threadIdx.x;
    float v0 = xr[tid], v1 = xr[tid + 256], v2 = xr[tid + 512];
    float s  = v0 + v1 + v2;
    float s2 = v0 * v0 + v1 * v1 + v2 * v2;
    __shared__ float sh1[256], sh2[256];
    sh1[tid] = s; sh2[tid] = s2;
    __syncthreads();
    for (int o = 128; o > 0; o >>= 1) {
        if (tid < o) { sh1[tid] += sh1[tid + o]; sh2[tid] += sh2[tid + o]; }
        __syncthreads();
    }
    float mu  = sh1[0] * (1.0f / D_);
    float var = sh2[0] * (1.0f / D_) - mu * mu;
    float r   = rsqrtf(var + 1e-6f);
    yr[tid]       = __float2half((v0 - mu) * r * g[tid]       + be[tid]);
    yr[tid + 256] = __float2half((v1 - mu) * r * g[tid + 256] + be[tid + 256]);
    yr[tid + 512] = __float2half((v2 - mu) * r * g[tid + 512] + be[tid + 512]);
}

// ---------------- fp16 mma.sync GEMM ----------------
#define TSH   40
#define STG_H (128 * TSH)
template <int EPI, typename OutT>
__global__ void __launch_bounds__(128) tgemm(const __half* __restrict__ A,
                                             const __half* __restrict__ BT,
                                             const float* __restrict__ bias,
                                             const float* __restrict__ res,
                                             OutT* __restrict__ C,
                                             int M, int N, int K) {
    extern __shared__ __half smh[];
    __half* As = smh;
    __half* Bs = smh + 3 * STG_H;

    int tid = threadIdx.x;
    int lane = tid & 31, wid = tid >> 5;
    int warpM = wid >> 1, warpN = wid & 1;
    int g = lane >> 2, t4 = lane & 3;
    int bm = blockIdx.y * 128, bn = blockIdx.x * 128;

    const __half* gA = A  + (size_t)bm * K;
    const __half* gB = BT + (size_t)bn * K;

    int lrow = tid >> 2;
    int c8   = tid & 3;

    float acc[4][8][4];
#pragma unroll
    for (int mf = 0; mf < 4; mf++)
#pragma unroll
        for (int nf = 0; nf < 8; nf++)
#pragma unroll
            for (int r = 0; r < 4; r++) acc[mf][nf][r] = 0.f;

    uint32_t sA0 = smem_u32(As), sB0 = smem_u32(Bs);
    int nc = K >> 5;

    auto issue = [&](int c, int s) {
        uint32_t sa = sA0 + (uint32_t)s * STG_H * 2;
        uint32_t sb = sB0 + (uint32_t)s * STG_H * 2;
        const __half* a0 = gA + (c << 5) + c8 * 8;
        const __half* b0 = gB + (c << 5) + c8 * 8;
#pragma unroll
        for (int i = 0; i < 4; i++) {
            int row = lrow + 32 * i;
            uint32_t off = (uint32_t)(row * TSH + c8 * 8) * 2;
            CP_ASYNC16(sa + off, a0 + (size_t)row * K);
            CP_ASYNC16(sb + off, b0 + (size_t)row * K);
        }
        CP_COMMIT();
    };

    issue(0, 0);
    if (nc > 1) issue(1, 1);

    for (int c = 0; c < nc; c++) {
        if (c + 1 < nc) { CP_WAIT(1); } else { CP_WAIT(0); }
        __syncthreads();
        if (c + 2 < nc) issue(c + 2, (c + 2) % 3);

        const __half* as = As + (c % 3) * STG_H;
        const __half* bs = Bs + (c % 3) * STG_H;
#pragma unroll
        for (int ko = 0; ko < 32; ko += 16) {
            uint32_t af[4][4];
#pragma unroll
            for (int mf = 0; mf < 4; mf++) {
                int r = warpM * 64 + mf * 16 + g;
                af[mf][0] = *(const uint32_t*)&as[r * TSH + ko + 2 * t4];
                af[mf][1] = *(const uint32_t*)&as[(r + 8) * TSH + ko + 2 * t4];
                af[mf][2] = *(const uint32_t*)&as[r * TSH + ko + 2 * t4 + 8];
                af[mf][3] = *(const uint32_t*)&as[(r + 8) * TSH + ko + 2 * t4 + 8];
            }
            uint32_t bf[8][2];
#pragma unroll
            for (int nf = 0; nf < 8; nf++) {
                int n = warpN * 64 + nf * 8 + g;
                bf[nf][0] = *(const uint32_t*)&bs[n * TSH + ko + 2 * t4];
                bf[nf][1] = *(const uint32_t*)&bs[n * TSH + ko + 2 * t4 + 8];
            }
#pragma unroll
            for (int mf = 0; mf < 4; mf++)
#pragma unroll
                for (int nf = 0; nf < 8; nf++)
                    mma_f16(acc[mf][nf], af[mf], bf[nf]);
        }
    }

#pragma unroll
    for (int mf = 0; mf < 4; mf++) {
        int r0 = bm + warpM * 64 + mf * 16 + g;
#pragma unroll
        for (int nf = 0; nf < 8; nf++) {
            int cc = bn + warpN * 64 + nf * 8 + t4 * 2;
            float b0 = bias[cc], b1 = bias[cc + 1];
            float v00 = acc[mf][nf][0] + b0, v01 = acc[mf][nf][1] + b1;
            float v10 = acc[mf][nf][2] + b0, v11 = acc[mf][nf][3] + b1;
            if (EPI == 1) {
                const float* rp0 = res + (size_t)r0 * N + cc;
                const float* rp1 = res + (size_t)(r0 + 8) * N + cc;
                v00 += rp0[0]; v01 += rp0[1];
                v10 += rp1[0]; v11 += rp1[1];
            }
            if (EPI == 2) {
                v00 = 0.5f * v00 * (1.0f + erff(v00 * 0.70710678118654752f));
                v01 = 0.5f * v01 * (1.0f + erff(v01 * 0.70710678118654752f));
                v10 = 0.5f * v10 * (1.0f + erff(v10 * 0.70710678118654752f));
                v11 = 0.5f * v11 * (1.0f + erff(v11 * 0.70710678118654752f));
            }
            if (sizeof(OutT) == 2) {
                __half2 h0 = __floats2half2_rn(v00, v01);
                __half2 h1 = __floats2half2_rn(v10, v11);
                *(__half2*)((__half*)C + (size_t)r0 * N + cc)       = h0;
                *(__half2*)((__half*)C + (size_t)(r0 + 8) * N + cc) = h1;
            } else {
                *(float2*)((float*)C + (size_t)r0 * N + cc)       = make_float2(v00, v01);
                *(float2*)((float*)C + (size_t)(r0 + 8) * N + cc) = make_float2(v10, v11);
            }
        }
    }
}

// ---------------- Ragged flash attention on fp16 mma.sync ------------------------
// grid (SMAX/64, H, B), 128 threads = 4 warps; warp w owns query rows w*16..+15.
// 16B-aligned half smem, stride 72 halves (row byte-stride 144 = 9*16).
// K/V loads are uint4 = 8 halves, matching the dg*8 index stride.
#define AH 72
__global__ void __launch_bounds__(128) attn_kernel(const __half* __restrict__ qkv,
                                                   const int* __restrict__ cu,
                                                   __half* __restrict__ out) {
    __shared__ __align__(16) __half Qs[64 * AH];
    __shared__ __align__(16) __half Ks[64 * AH];    // [key][dim]
    __shared__ __align__(16) __half VsT[64 * AH];   // [dim][key]
    __shared__ __align__(16) __half Ps[64 * AH];    // [query][key]

    int qt = blockIdx.x, h = blockIdx.y, b = blockIdx.z;
    int base = cu[b];
    int len  = cu[b + 1] - base;
    int q0   = qt * 64;
    if (q0 >= len) return;
    int nq = min(64, len - q0);

    int tid = threadIdx.x;
    int lane = tid & 31, wid = tid >> 5;
    int g = lane >> 2, t4 = lane & 3;
    int qw = wid * 16;

    const __half2 sc2 = __floats2half2_rn(0.125f, 0.125f);

    // load Q tile (scaled); zero pad rows. 8 halves per (qi, dg).
    for (int idx = tid; idx < 64 * 8; idx += 128) {
        int qi = idx >> 3, dg = idx & 7;
        __half2 v[4];
        if (qi < nq) {
            const __half2* src = (const __half2*)(qkv + (size_t)(base + q0 + qi) * 2304 + h * 64 + dg * 8);
#pragma unroll
            for (int i = 0; i < 4; i++) v[i] = __hmul2(src[i], sc2);
        } else {
#pragma unroll
            for (int i = 0; i < 4; i++) v[i] = __floats2half2_rn(0.f, 0.f);
        }
        __half2* dst = (__half2*)&Qs[qi * AH + dg * 8];
#pragma unroll
        for (int i = 0; i < 4; i++) dst[i] = v[i];
    }

    float m0 = -1e30f, m1 = -1e30f, l0 = 0.f, l1 = 0.f;
    float oacc[8][4];
#pragma unroll
    for (int nf = 0; nf < 8; nf++)
#pragma unroll
        for (int r = 0; r < 4; r++) oacc[nf][r] = 0.f;

    for (int k0 = 0; k0 < len; k0 += 64) {
        int nk = min(64, len - k0);
        __syncthreads();
        // K: [key][dim]; V transposed to [dim][key]. uint4 = 8 halves per (j, dg).
        for (int idx = tid; idx < 64 * 8; idx += 128) {
            int j = idx >> 3, dg = idx & 7;
            if (j < nk) {
                size_t r = (size_t)(base + k0 + j) * 2304 + h * 64 + dg * 8;
                uint4 kb = *(const uint4*)(qkv + r + 768);
                *(uint4*)&Ks[j * AH + dg * 8] = kb;
                union { uint4 u; __half hh[8]; } vb;
                vb.u = *(const uint4*)(qkv + r + 1536);
#pragma unroll
                for (int i = 0; i < 8; i++) VsT[(dg * 8 + i) * AH + j] = vb.hh[i];
            } else {
                *(uint4*)&Ks[j * AH + dg * 8] = make_uint4(0, 0, 0, 0);
#pragma unroll
                for (int i = 0; i < 8; i++) VsT[(dg * 8 + i) * AH + j] = __float2half(0.f);
            }
        }
        __syncthreads();

        // S = Q @ K^T
        float sacc[8][4];
#pragma unroll
        for (int nf = 0; nf < 8; nf++)
#pragma unroll
            for (int r = 0; r < 4; r++) sacc[nf][r] = 0.f;
#pragma unroll
        for (int kk = 0; kk < 64; kk += 16) {
            uint32_t af[4];
            af[0] = *(const uint32_t*)&Qs[(qw + g) * AH + kk + 2 * t4];
            af[1] = *(const uint32_t*)&Qs[(qw + g + 8) * AH + kk + 2 * t4];
            af[2] = *(const uint32_t*)&Qs[(qw + g) * AH + kk + 2 * t4 + 8];
            af[3] = *(const uint32_t*)&Qs[(qw + g + 8) * AH + kk + 2 * t4 + 8];
#pragma unroll
            for (int nf = 0; nf < 8; nf++) {
                uint32_t bf[2];
                bf[0] = *(const uint32_t*)&Ks[(nf * 8 + g) * AH + kk + 2 * t4];
                bf[1] = *(const uint32_t*)&Ks[(nf * 8 + g) * AH + kk + 2 * t4 + 8];
                mma_f16(sacc[nf], af, bf);
            }
        }

        // mask invalid keys
#pragma unroll
        for (int nf = 0; nf < 8; nf++) {
            int j = nf * 8 + 2 * t4;
            if (j >= nk)     { sacc[nf][0] = -1e30f; sacc[nf][2] = -1e30f; }
            if (j + 1 >= nk) { sacc[nf][1] = -1e30f; sacc[nf][3] = -1e30f; }
        }

        float tm0 = -1e30f, tm1 = -1e30f;
#pragma unroll
        for (int nf = 0; nf < 8; nf++) {
            tm0 = fmaxf(tm0, fmaxf(sacc[nf][0], sacc[nf][1]));
            tm1 = fmaxf(tm1, fmaxf(sacc[nf][2], sacc[nf][3]));
        }
        tm0 = fmaxf(tm0, __shfl_xor_sync(0xffffffffu, tm0, 1));
        tm0 = fmaxf(tm0, __shfl_xor_sync(0xffffffffu, tm0, 2));
        tm1 = fmaxf(tm1, __shfl_xor_sync(0xffffffffu, tm1, 1));
        tm1 = fmaxf(tm1, __shfl_xor_sync(0xffffffffu, tm1, 2));

        float nm0 = fmaxf(m0, tm0), nm1 = fmaxf(m1, tm1);
        float sc0 = __expf(m0 - nm0), sc1 = __expf(m1 - nm1);

        float ls0 = 0.f, ls1 = 0.f;
#pragma unroll
        for (int nf = 0; nf < 8; nf++) {
            float p0 = __expf(sacc[nf][0] - nm0);
            float p1 = __expf(sacc[nf][1] - nm0);
            float p2 = __expf(sacc[nf][2] - nm1);
            float p3 = __expf(sacc[nf][3] - nm1);
            ls0 += p0 + p1; ls1 += p2 + p3;
            int cb = nf * 8 + 2 * t4;
            *(__half2*)&Ps[(qw + g) * AH + cb]     = __floats2half2_rn(p0, p1);
            *(__half2*)&Ps[(qw + g + 8) * AH + cb] = __floats2half2_rn(p2, p3);
        }
        ls0 += __shfl_xor_sync(0xffffffffu, ls0, 1);
        ls0 += __shfl_xor_sync(0xffffffffu, ls0, 2);
        ls1 += __shfl_xor_sync(0xffffffffu, ls1, 1);
        ls1 += __shfl_xor_sync(0xffffffffu, ls1, 2);
        l0 = l0 * sc0 + ls0;
        l1 = l1 * sc1 + ls1;
        m0 = nm0; m1 = nm1;

#pragma unroll
        for (int nf = 0; nf < 8; nf++) {
            oacc[nf][0] *= sc0; oacc[nf][1] *= sc0;
            oacc[nf][2] *= sc1; oacc[nf][3] *= sc1;
        }
        __syncwarp();   // warp-private Ps rows ready

        // O += P @ V
#pragma unroll
        for (int kk = 0; kk < 64; kk += 16) {
            uint32_t af[4];
            af[0] = *(const uint32_t*)&Ps[(qw + g) * AH + kk + 2 * t4];
            af[1] = *(const uint32_t*)&Ps[(qw + g + 8) * AH + kk + 2 * t4];
            af[2] = *(const uint32_t*)&Ps[(qw + g) * AH + kk + 2 * t4 + 8];
            af[3] = *(const uint32_t*)&Ps[(qw + g + 8) * AH + kk + 2 * t4 + 8];
#pragma unroll
            for (int nf = 0; nf < 8; nf++) {
                uint32_t bf[2];
                bf[0] = *(const uint32_t*)&VsT[(nf * 8 + g) * AH + kk + 2 * t4];
                bf[1] = *(const uint32_t*)&VsT[(nf * 8 + g) * AH + kk + 2 * t4 + 8];
                mma_f16(oacc[nf], af, bf);
            }
        }
    }

    float inv0 = 1.0f / l0, inv1 = 1.0f / l1;
    if (qw + g < nq) {
        __half* op = out + (size_t)(base + q0 + qw + g) * D_ + h * 64;
#pragma unroll
        for (int nf = 0; nf < 8; nf++) {
            int cc = nf * 8 + 2 * t4;
            *(__half2*)(op + cc) = __floats2half2_rn(oacc[nf][0] * inv0, oacc[nf][1] * inv0);
        }
    }
    if (qw + g + 8 < nq) {
        __half* op = out + (size_t)(base + q0 + qw + g + 8) * D_ + h * 64;
#pragma unroll
        for (int nf = 0; nf < 8; nf++) {
            int cc = nf * 8 + 2 * t4;
            *(__half2*)(op + cc) = __floats2half2_rn(oacc[nf][2] * inv1, oacc[nf][3] * inv1);
        }
    }
}

// ---------------- host launch ----------------
extern "C" void kernel_launch(void* const* d_in, const int* in_sizes, int n_in,
                              void* d_out, int out_size) {
    const float* x     = (const float*)d_in[0];
    const int*   cu    = (const int*)  d_in[1];
    const float* g1    = (const float*)d_in[2];
    const float* beta1 = (const float*)d_in[3];
    const float* Wqkv  = (const float*)d_in[4];
    const float* bqkv  = (const float*)d_in[5];
    const float* Wo    = (const float*)d_in[6];
    const float* bo    = (const float*)d_in[7];
    const float* g2    = (const float*)d_in[8];
    const float* beta2 = (const float*)d_in[9];
    const float* W1    = (const float*)d_in[10];
    const float* b_fc1 = (const float*)d_in[11];
    const float* W2    = (const float*)d_in[12];
    const float* b_fc2 = (const float*)d_in[13];
    float* out = (float*)d_out;

    int total = in_sizes[0] / D_;   // 6144
    int nb    = in_sizes[1] - 1;    // 8

    __half *xnh, *qkvh, *attnh, *midh, *wqkvTh, *woTh, *w1Th, *w2Th;
    float  *x2;
    cudaGetSymbolAddress((void**)&xnh,    g_xnh);
    cudaGetSymbolAddress((void**)&qkvh,   g_qkvh);
    cudaGetSymbolAddress((void**)&attnh,  g_attnh);
    cudaGetSymbolAddress((void**)&x2,     g_x2);
    cudaGetSymbolAddress((void**)&midh,   g_midh);
    cudaGetSymbolAddress((void**)&wqkvTh, g_WqkvTh);
    cudaGetSymbolAddress((void**)&woTh,   g_WoTh);
    cudaGetSymbolAddress((void**)&w1Th,   g_W1Th);
    cudaGetSymbolAddress((void**)&w2Th,   g_W2Th);

    int mb = total / 128;
    dim3 tb(32, 8);

    const int GEMM_SMEM = 2 * 3 * STG_H * 2;   // 61440 B
    cudaFuncSetAttribute((const void*)tgemm<0, __half>, cudaFuncAttributeMaxDynamicSharedMemorySize, GEMM_SMEM);
    cudaFuncSetAttribute((const void*)tgemm<1, float>,  cudaFuncAttributeMaxDynamicSharedMemorySize, GEMM_SMEM);
    cudaFuncSetAttribute((const void*)tgemm<2, __half>, cudaFuncAttributeMaxDynamicSharedMemorySize, GEMM_SMEM);

    transpose_h<<<dim3(3 * D_ / 32, D_ / 32), tb>>>(Wqkv, wqkvTh, D_, 3 * D_);
    transpose_h<<<dim3(D_ / 32, D_ / 32),     tb>>>(Wo,   woTh,   D_, D_);
    transpose_h<<<dim3(DFF_ / 32, D_ / 32),   tb>>>(W1,   w1Th,   D_, DFF_);
    transpose_h<<<dim3(D_ / 32, DFF_ / 32),   tb>>>(W2,   w2Th,   DFF_, D_);

    ln_kernel<<<total, 256>>>(x, g1, beta1, xnh);
    tgemm<0, __half><<<dim3(3 * D_ / 128, mb), 128, GEMM_SMEM>>>(
        xnh, wqkvTh, bqkv, nullptr, qkvh, total, 3 * D_, D_);
    attn_kernel<<<dim3(SMAX_ / 64, H_, nb), 128>>>(qkvh, cu, attnh);
    tgemm<1, float><<<dim3(D_ / 128, mb), 128, GEMM_SMEM>>>(
        attnh, woTh, bo, x, x2, total, D_, D_);
    ln_kernel<<<total, 256>>>(x2, g2, beta2, xnh);
    tgemm<2, __half><<<dim3(DFF_ / 128, mb), 128, GEMM_SMEM>>>(
        xnh, w1Th, b_fc1, nullptr, midh, total, DFF_, D_);
    tgemm<1, float><<<dim3(D_ / 128, mb), 128, GEMM_SMEM>>>(
        midh, w2Th, b_fc2, x2, out, total, D_, DFF_);
}

// round 11
// speedup vs baseline: 2.6844x; 1.0235x over previous
#include <cuda_runtime.h>
#include <cuda_fp16.h>
#include <math.h>
#include <stdint.h>

#define D_    768
#define H_    12
#define HD_   64
#define DFF_  3072
#define MAXT  8192
#define SMAX_ 1024

// ---------------- scratch (no allocations allowed) ----------------
__device__ __half g_xnh  [(size_t)MAXT * D_];
__device__ __half g_qkvh [(size_t)MAXT * 3 * D_];
__device__ __half g_attnh[(size_t)MAXT * D_];
__device__ float  g_x2   [(size_t)MAXT * D_];
__device__ __half g_midh [(size_t)MAXT * DFF_];
__device__ __half g_WqkvTh[(size_t)3 * D_ * D_];
__device__ __half g_WoTh  [(size_t)D_ * D_];
__device__ __half g_W1Th  [(size_t)DFF_ * D_];
__device__ __half g_W2Th  [(size_t)D_ * DFF_];

// ---------------- helpers ----------------
__device__ __forceinline__ uint32_t smem_u32(const void* p) {
    uint32_t a;
    asm("{ .reg .u64 t; cvta.to.shared.u64 t, %1; cvt.u32.u64 %0, t; }" : "=r"(a) : "l"(p));
    return a;
}
#define CP_ASYNC16(dst, src) \
    asm volatile("cp.async.cg.shared.global [%0], [%1], 16;" :: "r"(dst), "l"(src) : "memory")
#define CP_COMMIT() asm volatile("cp.async.commit_group;" ::: "memory")
#define CP_WAIT(n)  asm volatile("cp.async.wait_group %0;" :: "n"(n) : "memory")

__device__ __forceinline__ void mma_f16(float* c, const uint32_t* a, const uint32_t* b) {
    asm volatile(
        "mma.sync.aligned.m16n8k16.row.col.f32.f16.f16.f32 "
        "{%0,%1,%2,%3}, {%4,%5,%6,%7}, {%8,%9}, {%0,%1,%2,%3};"
        : "+f"(c[0]), "+f"(c[1]), "+f"(c[2]), "+f"(c[3])
        : "r"(a[0]), "r"(a[1]), "r"(a[2]), "r"(a[3]), "r"(b[0]), "r"(b[1]));
}

// ---------------- transpose + fp16 round ----------------
__global__ void __launch_bounds__(256) transpose_h(const float* __restrict__ W,
                                                   __half* __restrict__ WT,
                                                   int K, int N) {
    __shared__ float tile[32][33];
    int tx = threadIdx.x, ty = threadIdx.y;
    int n0 = blockIdx.x * 32, k0 = blockIdx.y * 32;
#pragma unroll
    for (int i = 0; i < 4; i++)
        tile[ty + 8 * i][tx] = W[(size_t)(k0 + ty + 8 * i) * N + n0 + tx];
    __syncthreads();
#pragma unroll
    for (int i = 0; i < 4; i++)
        WT[(size_t)(n0 + ty + 8 * i) * K + k0 + tx] = __float2half(tile[tx][ty + 8 * i]);
}

// ---------------- LayerNorm (warp-shuffle reduction, fp16 output) ----------------
__global__ void __launch_bounds__(256) ln_kernel(const float* __restrict__ x,
                                                 const float* __restrict__ g,
                                                 const float* __restrict__ be,
                                                 __half* __restrict__ y) {
    int t = blockIdx.x;
    const float* xr = x + (size_t)t * D_;
    __half*      yr = y + (size_t)t * D_;
    int tid  = threadIdx.x;
    int lane = tid & 31, warp = tid >> 5;
    float v0 = xr[tid], v1 = xr[tid + 256], v2 = xr[tid + 512];
    float s  = v0 + v1 + v2;
    float s2 = v0 * v0 + v1 * v1 + v2 * v2;
#pragma unroll
    for (int off = 16; off >= 1; off >>= 1) {
        s  += __shfl_xor_sync(0xffffffffu, s,  off);
        s2 += __shfl_xor_sync(0xffffffffu, s2, off);
    }
    __shared__ float w1[8], w2[8], bc[2];
    if (lane == 0) { w1[warp] = s; w2[warp] = s2; }
    __syncthreads();
    if (warp == 0) {
        float a = (lane < 8) ? w1[lane] : 0.f;
        float b = (lane < 8) ? w2[lane] : 0.f;
#pragma unroll
        for (int off = 4; off >= 1; off >>= 1) {
            a += __shfl_xor_sync(0xffffffffu, a, off);
            b += __shfl_xor_sync(0xffffffffu, b, off);
        }
        if (lane == 0) {
            float mu  = a * (1.0f / D_);
            float var = b * (1.0f / D_) - mu * mu;
            bc[0] = mu;
            bc[1] = rsqrtf(var + 1e-6f);
        }
    }
    __syncthreads();
    float mu = bc[0], r = bc[1];
    yr[tid]       = __float2half((v0 - mu) * r * g[tid]       + be[tid]);
    yr[tid + 256] = __float2half((v1 - mu) * r * g[tid + 256] + be[tid + 256]);
    yr[tid + 512] = __float2half((v2 - mu) * r * g[tid + 512] + be[tid + 512]);
}

// ---------------- fp16 mma.sync GEMM ----------------
#define TSH   40
#define STG_H (128 * TSH)
template <int EPI, typename OutT>
__global__ void __launch_bounds__(128) tgemm(const __half* __restrict__ A,
                                             const __half* __restrict__ BT,
                                             const float* __restrict__ bias,
                                             const float* __restrict__ res,
                                             OutT* __restrict__ C,
                                             int M, int N, int K) {
    extern __shared__ __half smh[];
    __half* As = smh;
    __half* Bs = smh + 3 * STG_H;

    int tid = threadIdx.x;
    int lane = tid & 31, wid = tid >> 5;
    int warpM = wid >> 1, warpN = wid & 1;
    int g = lane >> 2, t4 = lane & 3;
    int bm = blockIdx.y * 128, bn = blockIdx.x * 128;

    const __half* gA = A  + (size_t)bm * K;
    const __half* gB = BT + (size_t)bn * K;

    int lrow = tid >> 2;
    int c8   = tid & 3;

    float acc[4][8][4];
#pragma unroll
    for (int mf = 0; mf < 4; mf++)
#pragma unroll
        for (int nf = 0; nf < 8; nf++)
#pragma unroll
            for (int r = 0; r < 4; r++) acc[mf][nf][r] = 0.f;

    uint32_t sA0 = smem_u32(As), sB0 = smem_u32(Bs);
    int nc = K >> 5;

    auto issue = [&](int c, int s) {
        uint32_t sa = sA0 + (uint32_t)s * STG_H * 2;
        uint32_t sb = sB0 + (uint32_t)s * STG_H * 2;
        const __half* a0 = gA + (c << 5) + c8 * 8;
        const __half* b0 = gB + (c << 5) + c8 * 8;
#pragma unroll
        for (int i = 0; i < 4; i++) {
            int row = lrow + 32 * i;
            uint32_t off = (uint32_t)(row * TSH + c8 * 8) * 2;
            CP_ASYNC16(sa + off, a0 + (size_t)row * K);
            CP_ASYNC16(sb + off, b0 + (size_t)row * K);
        }
        CP_COMMIT();
    };

    issue(0, 0);
    if (nc > 1) issue(1, 1);

    for (int c = 0; c < nc; c++) {
        if (c + 1 < nc) { CP_WAIT(1); } else { CP_WAIT(0); }
        __syncthreads();
        if (c + 2 < nc) issue(c + 2, (c + 2) % 3);

        const __half* as = As + (c % 3) * STG_H;
        const __half* bs = Bs + (c % 3) * STG_H;
#pragma unroll
        for (int ko = 0; ko < 32; ko += 16) {
            uint32_t af[4][4];
#pragma unroll
            for (int mf = 0; mf < 4; mf++) {
                int r = warpM * 64 + mf * 16 + g;
                af[mf][0] = *(const uint32_t*)&as[r * TSH + ko + 2 * t4];
                af[mf][1] = *(const uint32_t*)&as[(r + 8) * TSH + ko + 2 * t4];
                af[mf][2] = *(const uint32_t*)&as[r * TSH + ko + 2 * t4 + 8];
                af[mf][3] = *(const uint32_t*)&as[(r + 8) * TSH + ko + 2 * t4 + 8];
            }
            uint32_t bf[8][2];
#pragma unroll
            for (int nf = 0; nf < 8; nf++) {
                int n = warpN * 64 + nf * 8 + g;
                bf[nf][0] = *(const uint32_t*)&bs[n * TSH + ko + 2 * t4];
                bf[nf][1] = *(const uint32_t*)&bs[n * TSH + ko + 2 * t4 + 8];
            }
#pragma unroll
            for (int mf = 0; mf < 4; mf++)
#pragma unroll
                for (int nf = 0; nf < 8; nf++)
                    mma_f16(acc[mf][nf], af[mf], bf[nf]);
        }
    }

#pragma unroll
    for (int mf = 0; mf < 4; mf++) {
        int r0 = bm + warpM * 64 + mf * 16 + g;
#pragma unroll
        for (int nf = 0; nf < 8; nf++) {
            int cc = bn + warpN * 64 + nf * 8 + t4 * 2;
            float b0 = bias[cc], b1 = bias[cc + 1];
            float v00 = acc[mf][nf][0] + b0, v01 = acc[mf][nf][1] + b1;
            float v10 = acc[mf][nf][2] + b0, v11 = acc[mf][nf][3] + b1;
            if (EPI == 1) {
                const float* rp0 = res + (size_t)r0 * N + cc;
                const float* rp1 = res + (size_t)(r0 + 8) * N + cc;
                v00 += rp0[0]; v01 += rp0[1];
                v10 += rp1[0]; v11 += rp1[1];
            }
            if (EPI == 2) {
                v00 = 0.5f * v00 * (1.0f + erff(v00 * 0.70710678118654752f));
                v01 = 0.5f * v01 * (1.0f + erff(v01 * 0.70710678118654752f));
                v10 = 0.5f * v10 * (1.0f + erff(v10 * 0.70710678118654752f));
                v11 = 0.5f * v11 * (1.0f + erff(v11 * 0.70710678118654752f));
            }
            if (sizeof(OutT) == 2) {
                __half2 h0 = __floats2half2_rn(v00, v01);
                __half2 h1 = __floats2half2_rn(v10, v11);
                *(__half2*)((__half*)C + (size_t)r0 * N + cc)       = h0;
                *(__half2*)((__half*)C + (size_t)(r0 + 8) * N + cc) = h1;
            } else {
                *(float2*)((float*)C + (size_t)r0 * N + cc)       = make_float2(v00, v01);
                *(float2*)((float*)C + (size_t)(r0 + 8) * N + cc) = make_float2(v10, v11);
            }
        }
    }
}

// ---------------- Ragged flash attention on fp16 mma.sync ------------------------
#define AH 72
__global__ void __launch_bounds__(128) attn_kernel(const __half* __restrict__ qkv,
                                                   const int* __restrict__ cu,
                                                   __half* __restrict__ out) {
    __shared__ __align__(16) __half Qs[64 * AH];
    __shared__ __align__(16) __half Ks[64 * AH];    // [key][dim]
    __shared__ __align__(16) __half VsT[64 * AH];   // [dim][key]
    __shared__ __align__(16) __half Ps[64 * AH];    // [query][key]

    int qt = blockIdx.x, h = blockIdx.y, b = blockIdx.z;
    int base = cu[b];
    int len  = cu[b + 1] - base;
    int q0   = qt * 64;
    if (q0 >= len) return;
    int nq = min(64, len - q0);

    int tid = threadIdx.x;
    int lane = tid & 31, wid = tid >> 5;
    int g = lane >> 2, t4 = lane & 3;
    int qw = wid * 16;

    const __half2 sc2 = __floats2half2_rn(0.125f, 0.125f);

    for (int idx = tid; idx < 64 * 8; idx += 128) {
        int qi = idx >> 3, dg = idx & 7;
        __half2 v[4];
        if (qi < nq) {
            const __half2* src = (const __half2*)(qkv + (size_t)(base + q0 + qi) * 2304 + h * 64 + dg * 8);
#pragma unroll
            for (int i = 0; i < 4; i++) v[i] = __hmul2(src[i], sc2);
        } else {
#pragma unroll
            for (int i = 0; i < 4; i++) v[i] = __floats2half2_rn(0.f, 0.f);
        }
        __half2* dst = (__half2*)&Qs[qi * AH + dg * 8];
#pragma unroll
        for (int i = 0; i < 4; i++) dst[i] = v[i];
    }

    float m0 = -1e30f, m1 = -1e30f, l0 = 0.f, l1 = 0.f;
    float oacc[8][4];
#pragma unroll
    for (int nf = 0; nf < 8; nf++)
#pragma unroll
        for (int r = 0; r < 4; r++) oacc[nf][r] = 0.f;

    for (int k0 = 0; k0 < len; k0 += 64) {
        int nk = min(64, len - k0);
        __syncthreads();
        for (int idx = tid; idx < 64 * 8; idx += 128) {
            int j = idx >> 3, dg = idx & 7;
            if (j < nk) {
                size_t r = (size_t)(base + k0 + j) * 2304 + h * 64 + dg * 8;
                uint4 kb = *(const uint4*)(qkv + r + 768);
                *(uint4*)&Ks[j * AH + dg * 8] = kb;
                union { uint4 u; __half hh[8]; } vb;
                vb.u = *(const uint4*)(qkv + r + 1536);
#pragma unroll
                for (int i = 0; i < 8; i++) VsT[(dg * 8 + i) * AH + j] = vb.hh[i];
            } else {
                *(uint4*)&Ks[j * AH + dg * 8] = make_uint4(0, 0, 0, 0);
#pragma unroll
                for (int i = 0; i < 8; i++) VsT[(dg * 8 + i) * AH + j] = __float2half(0.f);
            }
        }
        __syncthreads();

        float sacc[8][4];
#pragma unroll
        for (int nf = 0; nf < 8; nf++)
#pragma unroll
            for (int r = 0; r < 4; r++) sacc[nf][r] = 0.f;
#pragma unroll
        for (int kk = 0; kk < 64; kk += 16) {
            uint32_t af[4];
            af[0] = *(const uint32_t*)&Qs[(qw + g) * AH + kk + 2 * t4];
            af[1] = *(const uint32_t*)&Qs[(qw + g + 8) * AH + kk + 2 * t4];
            af[2] = *(const uint32_t*)&Qs[(qw + g) * AH + kk + 2 * t4 + 8];
            af[3] = *(const uint32_t*)&Qs[(qw + g + 8) * AH + kk + 2 * t4 + 8];
#pragma unroll
            for (int nf = 0; nf < 8; nf++) {
                uint32_t bf[2];
                bf[0] = *(const uint32_t*)&Ks[(nf * 8 + g) * AH + kk + 2 * t4];
                bf[1] = *(const uint32_t*)&Ks[(nf * 8 + g) * AH + kk + 2 * t4 + 8];
                mma_f16(sacc[nf], af, bf);
            }
        }

#pragma unroll
        for (int nf = 0; nf < 8; nf++) {
            int j = nf * 8 + 2 * t4;
            if (j >= nk)     { sacc[nf][0] = -1e30f; sacc[nf][2] = -1e30f; }
            if (j + 1 >= nk) { sacc[nf][1] = -1e30f; sacc[nf][3] = -1e30f; }
        }

        float tm0 = -1e30f, tm1 = -1e30f;
#pragma unroll
        for (int nf = 0; nf < 8; nf++) {
            tm0 = fmaxf(tm0, fmaxf(sacc[nf][0], sacc[nf][1]));
            tm1 = fmaxf(tm1, fmaxf(sacc[nf][2], sacc[nf][3]));
        }
        tm0 = fmaxf(tm0, __shfl_xor_sync(0xffffffffu, tm0, 1));
        tm0 = fmaxf(tm0, __shfl_xor_sync(0xffffffffu, tm0, 2));
        tm1 = fmaxf(tm1, __shfl_xor_sync(0xffffffffu, tm1, 1));
        tm1 = fmaxf(tm1, __shfl_xor_sync(0xffffffffu, tm1, 2));

        float nm0 = fmaxf(m0, tm0), nm1 = fmaxf(m1, tm1);
        float sc0 = __expf(m0 - nm0), sc1 = __expf(m1 - nm1);

        float ls0 = 0.f, ls1 = 0.f;
#pragma unroll
        for (int nf = 0; nf < 8; nf++) {
            float p0 = __expf(sacc[nf][0] - nm0);
            float p1 = __expf(sacc[nf][1] - nm0);
            float p2 = __expf(sacc[nf][2] - nm1);
            float p3 = __expf(sacc[nf][3] - nm1);
            ls0 += p0 + p1; ls1 += p2 + p3;
            int cb = nf * 8 + 2 * t4;
            *(__half2*)&Ps[(qw + g) * AH + cb]     = __floats2half2_rn(p0, p1);
            *(__half2*)&Ps[(qw + g + 8) * AH + cb] = __floats2half2_rn(p2, p3);
        }
        ls0 += __shfl_xor_sync(0xffffffffu, ls0, 1);
        ls0 += __shfl_xor_sync(0xffffffffu, ls0, 2);
        ls1 += __shfl_xor_sync(0xffffffffu, ls1, 1);
        ls1 += __shfl_xor_sync(0xffffffffu, ls1, 2);
        l0 = l0 * sc0 + ls0;
        l1 = l1 * sc1 + ls1;
        m0 = nm0; m1 = nm1;

#pragma unroll
        for (int nf = 0; nf < 8; nf++) {
            oacc[nf][0] *= sc0; oacc[nf][1] *= sc0;
            oacc[nf][2] *= sc1; oacc[nf][3] *= sc1;
        }
        __syncwarp();

#pragma unroll
        for (int kk = 0; kk < 64; kk += 16) {
            uint32_t af[4];
            af[0] = *(const uint32_t*)&Ps[(qw + g) * AH + kk + 2 * t4];
            af[1] = *(const uint32_t*)&Ps[(qw + g + 8) * AH + kk + 2 * t4];
            af[2] = *(const uint32_t*)&Ps[(qw + g) * AH + kk + 2 * t4 + 8];
            af[3] = *(const uint32_t*)&Ps[(qw + g + 8) * AH + kk + 2 * t4 + 8];
#pragma unroll
            for (int nf = 0; nf < 8; nf++) {
                uint32_t bf[2];
                bf[0] = *(const uint32_t*)&VsT[(nf * 8 + g) * AH + kk + 2 * t4];
                bf[1] = *(const uint32_t*)&VsT[(nf * 8 + g) * AH + kk + 2 * t4 + 8];
                mma_f16(oacc[nf], af, bf);
            }
        }
    }

    float inv0 = 1.0f / l0, inv1 = 1.0f / l1;
    if (qw + g < nq) {
        __half* op = out + (size_t)(base + q0 + qw + g) * D_ + h * 64;
#pragma unroll
        for (int nf = 0; nf < 8; nf++) {
            int cc = nf * 8 + 2 * t4;
            *(__half2*)(op + cc) = __floats2half2_rn(oacc[nf][0] * inv0, oacc[nf][1] * inv0);
        }
    }
    if (qw + g + 8 < nq) {
        __half* op = out + (size_t)(base + q0 + qw + g + 8) * D_ + h * 64;
#pragma unroll
        for (int nf = 0; nf < 8; nf++) {
            int cc = nf * 8 + 2 * t4;
            *(__half2*)(op + cc) = __floats2half2_rn(oacc[nf][2] * inv1, oacc[nf][3] * inv1);
        }
    }
}

// ---------------- host launch ----------------
extern "C" void kernel_launch(void* const* d_in, const int* in_sizes, int n_in,
                              void* d_out, int out_size) {
    const float* x     = (const float*)d_in[0];
    const int*   cu    = (const int*)  d_in[1];
    const float* g1    = (const float*)d_in[2];
    const float* beta1 = (const float*)d_in[3];
    const float* Wqkv  = (const float*)d_in[4];
    const float* bqkv  = (const float*)d_in[5];
    const float* Wo    = (const float*)d_in[6];
    const float* bo    = (const float*)d_in[7];
    const float* g2    = (const float*)d_in[8];
    const float* beta2 = (const float*)d_in[9];
    const float* W1    = (const float*)d_in[10];
    const float* b_fc1 = (const float*)d_in[11];
    const float* W2    = (const float*)d_in[12];
    const float* b_fc2 = (const float*)d_in[13];
    float* out = (float*)d_out;

    int total = in_sizes[0] / D_;   // 6144
    int nb    = in_sizes[1] - 1;    // 8

    __half *xnh, *qkvh, *attnh, *midh, *wqkvTh, *woTh, *w1Th, *w2Th;
    float  *x2;
    cudaGetSymbolAddress((void**)&xnh,    g_xnh);
    cudaGetSymbolAddress((void**)&qkvh,   g_qkvh);
    cudaGetSymbolAddress((void**)&attnh,  g_attnh);
    cudaGetSymbolAddress((void**)&x2,     g_x2);
    cudaGetSymbolAddress((void**)&midh,   g_midh);
    cudaGetSymbolAddress((void**)&wqkvTh, g_WqkvTh);
    cudaGetSymbolAddress((void**)&woTh,   g_WoTh);
    cudaGetSymbolAddress((void**)&w1Th,   g_W1Th);
    cudaGetSymbolAddress((void**)&w2Th,   g_W2Th);

    // one-time stream/event setup (outside capture: first call is the
    // correctness run). No device memory is allocated here.
    static cudaStream_t s1 = nullptr, s2 = nullptr;
    static cudaEvent_t evF = nullptr, ev1 = nullptr, ev2 = nullptr;
    if (s1 == nullptr) {
        cudaStreamCreateWithFlags(&s1, cudaStreamNonBlocking);
        cudaStreamCreateWithFlags(&s2, cudaStreamNonBlocking);
        cudaEventCreateWithFlags(&evF, cudaEventDisableTiming);
        cudaEventCreateWithFlags(&ev1, cudaEventDisableTiming);
        cudaEventCreateWithFlags(&ev2, cudaEventDisableTiming);
    }

    int mb = total / 128;
    dim3 tb(32, 8);

    const int GEMM_SMEM = 2 * 3 * STG_H * 2;   // 61440 B
    cudaFuncSetAttribute((const void*)tgemm<0, __half>, cudaFuncAttributeMaxDynamicSharedMemorySize, GEMM_SMEM);
    cudaFuncSetAttribute((const void*)tgemm<1, float>,  cudaFuncAttributeMaxDynamicSharedMemorySize, GEMM_SMEM);
    cudaFuncSetAttribute((const void*)tgemm<2, __half>, cudaFuncAttributeMaxDynamicSharedMemorySize, GEMM_SMEM);

    // fork: weight transposes on side streams, overlapped with LN1 / early pipeline
    cudaEventRecord(evF, 0);
    cudaStreamWaitEvent(s1, evF, 0);
    cudaStreamWaitEvent(s2, evF, 0);
    transpose_h<<<dim3(3 * D_ / 32, D_ / 32), tb, 0, s1>>>(Wqkv, wqkvTh, D_, 3 * D_);
    transpose_h<<<dim3(D_ / 32, D_ / 32),     tb, 0, s1>>>(Wo,   woTh,   D_, D_);
    cudaEventRecord(ev1, s1);
    transpose_h<<<dim3(DFF_ / 32, D_ / 32),   tb, 0, s2>>>(W1,   w1Th,   D_, DFF_);
    transpose_h<<<dim3(D_ / 32, DFF_ / 32),   tb, 0, s2>>>(W2,   w2Th,   DFF_, D_);
    cudaEventRecord(ev2, s2);

    // main stream
    ln_kernel<<<total, 256>>>(x, g1, beta1, xnh);
    cudaStreamWaitEvent(0, ev1, 0);   // need WqkvT (and WoT soon after)
    tgemm<0, __half><<<dim3(3 * D_ / 128, mb), 128, GEMM_SMEM>>>(
        xnh, wqkvTh, bqkv, nullptr, qkvh, total, 3 * D_, D_);
    attn_kernel<<<dim3(SMAX_ / 64, H_, nb), 128>>>(qkvh, cu, attnh);
    tgemm<1, float><<<dim3(D_ / 128, mb), 128, GEMM_SMEM>>>(
        attnh, woTh, bo, x, x2, total, D_, D_);
    ln_kernel<<<total, 256>>>(x2, g2, beta2, xnh);
    cudaStreamWaitEvent(0, ev2, 0);   // need W1T/W2T
    tgemm<2, __half><<<dim3(DFF_ / 128, mb), 128, GEMM_SMEM>>>(
        xnh, w1Th, b_fc1, nullptr, midh, total, DFF_, D_);
    tgemm<1, float><<<dim3(D_ / 128, mb), 128, GEMM_SMEM>>>(
        midh, w2Th, b_fc2, x2, out, total, D_, DFF_);
}

// round 12
// speedup vs baseline: 3.2263x; 1.2018x over previous
#include <cuda_runtime.h>
#include <cuda_fp16.h>
#include <math.h>
#include <stdint.h>

#define D_    768
#define H_    12
#define HD_   64
#define DFF_  3072
#define MAXT  8192
#define SMAX_ 1024

// ---------------- scratch (no allocations allowed) ----------------
__device__ __half g_xnh  [(size_t)MAXT * D_];
__device__ __half g_qkvh [(size_t)MAXT * 3 * D_];
__device__ __half g_attnh[(size_t)MAXT * D_];
__device__ float  g_x2   [(size_t)MAXT * D_];
__device__ __half g_midh [(size_t)MAXT * DFF_];
__device__ __half g_WqkvTh[(size_t)3 * D_ * D_];
__device__ __half g_WoTh  [(size_t)D_ * D_];
__device__ __half g_W1Th  [(size_t)DFF_ * D_];
__device__ __half g_W2Th  [(size_t)D_ * DFF_];

// ---------------- helpers ----------------
__device__ __forceinline__ uint32_t smem_u32(const void* p) {
    uint32_t a;
    asm("{ .reg .u64 t; cvta.to.shared.u64 t, %1; cvt.u32.u64 %0, t; }" : "=r"(a) : "l"(p));
    return a;
}
#define CP_ASYNC16(dst, src) \
    asm volatile("cp.async.cg.shared.global [%0], [%1], 16;" :: "r"(dst), "l"(src) : "memory")
#define CP_ASYNC16Z(dst, src) \
    asm volatile("cp.async.cg.shared.global [%0], [%1], 16, 0;" :: "r"(dst), "l"(src) : "memory")
#define CP_COMMIT() asm volatile("cp.async.commit_group;" ::: "memory")
#define CP_WAIT(n)  asm volatile("cp.async.wait_group %0;" :: "n"(n) : "memory")

__device__ __forceinline__ void mma_f16(float* c, const uint32_t* a, const uint32_t* b) {
    asm volatile(
        "mma.sync.aligned.m16n8k16.row.col.f32.f16.f16.f32 "
        "{%0,%1,%2,%3}, {%4,%5,%6,%7}, {%8,%9}, {%0,%1,%2,%3};"
        : "+f"(c[0]), "+f"(c[1]), "+f"(c[2]), "+f"(c[3])
        : "r"(a[0]), "r"(a[1]), "r"(a[2]), "r"(a[3]), "r"(b[0]), "r"(b[1]));
}
__device__ __forceinline__ void ldsm_x2_t(uint32_t& r0, uint32_t& r1, uint32_t a) {
    asm volatile("ldmatrix.sync.aligned.m8n8.x2.trans.shared.b16 {%0,%1}, [%2];"
                 : "=r"(r0), "=r"(r1) : "r"(a));
}
__device__ __forceinline__ uint32_t h2u(float a, float b) {
    __half2 t = __floats2half2_rn(a, b);
    return *(uint32_t*)&t;
}

// ---------------- transpose + fp16 round ----------------
__global__ void __launch_bounds__(256) transpose_h(const float* __restrict__ W,
                                                   __half* __restrict__ WT,
                                                   int K, int N) {
    __shared__ float tile[32][33];
    int tx = threadIdx.x, ty = threadIdx.y;
    int n0 = blockIdx.x * 32, k0 = blockIdx.y * 32;
#pragma unroll
    for (int i = 0; i < 4; i++)
        tile[ty + 8 * i][tx] = W[(size_t)(k0 + ty + 8 * i) * N + n0 + tx];
    __syncthreads();
#pragma unroll
    for (int i = 0; i < 4; i++)
        WT[(size_t)(n0 + ty + 8 * i) * K + k0 + tx] = __float2half(tile[tx][ty + 8 * i]);
}

// ---------------- LayerNorm (warp-shuffle reduction, fp16 output) ----------------
__global__ void __launch_bounds__(256) ln_kernel(const float* __restrict__ x,
                                                 const float* __restrict__ g,
                                                 const float* __restrict__ be,
                                                 __half* __restrict__ y) {
    int t = blockIdx.x;
    const float* xr = x + (size_t)t * D_;
    __half*      yr = y + (size_t)t * D_;
    int tid  = threadIdx.x;
    int lane = tid & 31, warp = tid >> 5;
    float v0 = xr[tid], v1 = xr[tid + 256], v2 = xr[tid + 512];
    float s  = v0 + v1 + v2;
    float s2 = v0 * v0 + v1 * v1 + v2 * v2;
#pragma unroll
    for (int off = 16; off >= 1; off >>= 1) {
        s  += __shfl_xor_sync(0xffffffffu, s,  off);
        s2 += __shfl_xor_sync(0xffffffffu, s2, off);
    }
    __shared__ float w1[8], w2[8], bc[2];
    if (lane == 0) { w1[warp] = s; w2[warp] = s2; }
    __syncthreads();
    if (warp == 0) {
        float a = (lane < 8) ? w1[lane] : 0.f;
        float b = (lane < 8) ? w2[lane] : 0.f;
#pragma unroll
        for (int off = 4; off >= 1; off >>= 1) {
            a += __shfl_xor_sync(0xffffffffu, a, off);
            b += __shfl_xor_sync(0xffffffffu, b, off);
        }
        if (lane == 0) {
            float mu  = a * (1.0f / D_);
            float var = b * (1.0f / D_) - mu * mu;
            bc[0] = mu;
            bc[1] = rsqrtf(var + 1e-6f);
        }
    }
    __syncthreads();
    float mu = bc[0], r = bc[1];
    yr[tid]       = __float2half((v0 - mu) * r * g[tid]       + be[tid]);
    yr[tid + 256] = __float2half((v1 - mu) * r * g[tid + 256] + be[tid + 256]);
    yr[tid + 512] = __float2half((v2 - mu) * r * g[tid + 512] + be[tid + 512]);
}

// ---------------- fp16 mma.sync GEMM (unchanged, proven) ----------------
#define TSH   40
#define STG_H (128 * TSH)
template <int EPI, typename OutT>
__global__ void __launch_bounds__(128) tgemm(const __half* __restrict__ A,
                                             const __half* __restrict__ BT,
                                             const float* __restrict__ bias,
                                             const float* __restrict__ res,
                                             OutT* __restrict__ C,
                                             int M, int N, int K) {
    extern __shared__ __half smh[];
    __half* As = smh;
    __half* Bs = smh + 3 * STG_H;

    int tid = threadIdx.x;
    int lane = tid & 31, wid = tid >> 5;
    int warpM = wid >> 1, warpN = wid & 1;
    int g = lane >> 2, t4 = lane & 3;
    int bm = blockIdx.y * 128, bn = blockIdx.x * 128;

    const __half* gA = A  + (size_t)bm * K;
    const __half* gB = BT + (size_t)bn * K;

    int lrow = tid >> 2;
    int c8   = tid & 3;

    float acc[4][8][4];
#pragma unroll
    for (int mf = 0; mf < 4; mf++)
#pragma unroll
        for (int nf = 0; nf < 8; nf++)
#pragma unroll
            for (int r = 0; r < 4; r++) acc[mf][nf][r] = 0.f;

    uint32_t sA0 = smem_u32(As), sB0 = smem_u32(Bs);
    int nc = K >> 5;

    auto issue = [&](int c, int s) {
        uint32_t sa = sA0 + (uint32_t)s * STG_H * 2;
        uint32_t sb = sB0 + (uint32_t)s * STG_H * 2;
        const __half* a0 = gA + (c << 5) + c8 * 8;
        const __half* b0 = gB + (c << 5) + c8 * 8;
#pragma unroll
        for (int i = 0; i < 4; i++) {
            int row = lrow + 32 * i;
            uint32_t off = (uint32_t)(row * TSH + c8 * 8) * 2;
            CP_ASYNC16(sa + off, a0 + (size_t)row * K);
            CP_ASYNC16(sb + off, b0 + (size_t)row * K);
        }
        CP_COMMIT();
    };

    issue(0, 0);
    if (nc > 1) issue(1, 1);

    for (int c = 0; c < nc; c++) {
        if (c + 1 < nc) { CP_WAIT(1); } else { CP_WAIT(0); }
        __syncthreads();
        if (c + 2 < nc) issue(c + 2, (c + 2) % 3);

        const __half* as = As + (c % 3) * STG_H;
        const __half* bs = Bs + (c % 3) * STG_H;
#pragma unroll
        for (int ko = 0; ko < 32; ko += 16) {
            uint32_t af[4][4];
#pragma unroll
            for (int mf = 0; mf < 4; mf++) {
                int r = warpM * 64 + mf * 16 + g;
                af[mf][0] = *(const uint32_t*)&as[r * TSH + ko + 2 * t4];
                af[mf][1] = *(const uint32_t*)&as[(r + 8) * TSH + ko + 2 * t4];
                af[mf][2] = *(const uint32_t*)&as[r * TSH + ko + 2 * t4 + 8];
                af[mf][3] = *(const uint32_t*)&as[(r + 8) * TSH + ko + 2 * t4 + 8];
            }
            uint32_t bf[8][2];
#pragma unroll
            for (int nf = 0; nf < 8; nf++) {
                int n = warpN * 64 + nf * 8 + g;
                bf[nf][0] = *(const uint32_t*)&bs[n * TSH + ko + 2 * t4];
                bf[nf][1] = *(const uint32_t*)&bs[n * TSH + ko + 2 * t4 + 8];
            }
#pragma unroll
            for (int mf = 0; mf < 4; mf++)
#pragma unroll
                for (int nf = 0; nf < 8; nf++)
                    mma_f16(acc[mf][nf], af[mf], bf[nf]);
        }
    }

#pragma unroll
    for (int mf = 0; mf < 4; mf++) {
        int r0 = bm + warpM * 64 + mf * 16 + g;
#pragma unroll
        for (int nf = 0; nf < 8; nf++) {
            int cc = bn + warpN * 64 + nf * 8 + t4 * 2;
            float b0 = bias[cc], b1 = bias[cc + 1];
            float v00 = acc[mf][nf][0] + b0, v01 = acc[mf][nf][1] + b1;
            float v10 = acc[mf][nf][2] + b0, v11 = acc[mf][nf][3] + b1;
            if (EPI == 1) {
                const float* rp0 = res + (size_t)r0 * N + cc;
                const float* rp1 = res + (size_t)(r0 + 8) * N + cc;
                v00 += rp0[0]; v01 += rp0[1];
                v10 += rp1[0]; v11 += rp1[1];
            }
            if (EPI == 2) {
                v00 = 0.5f * v00 * (1.0f + erff(v00 * 0.70710678118654752f));
                v01 = 0.5f * v01 * (1.0f + erff(v01 * 0.70710678118654752f));
                v10 = 0.5f * v10 * (1.0f + erff(v10 * 0.70710678118654752f));
                v11 = 0.5f * v11 * (1.0f + erff(v11 * 0.70710678118654752f));
            }
            if (sizeof(OutT) == 2) {
                __half2 h0 = __floats2half2_rn(v00, v01);
                __half2 h1 = __floats2half2_rn(v10, v11);
                *(__half2*)((__half*)C + (size_t)r0 * N + cc)       = h0;
                *(__half2*)((__half*)C + (size_t)(r0 + 8) * N + cc) = h1;
            } else {
                *(float2*)((float*)C + (size_t)r0 * N + cc)       = make_float2(v00, v01);
                *(float2*)((float*)C + (size_t)(r0 + 8) * N + cc) = make_float2(v10, v11);
            }
        }
    }
}

// ---------------- Ragged flash attention: reg-P + ldmatrix V + cp.async ----------
// grid (SMAX/128, H, B), 256 threads = 8 warps; warp w owns query rows w*16..+15.
// Q [128][AH] loaded once (cp.async). K/V [64][AH] row-major, 2-stage cp.async ring.
// P never touches smem: S C-fragments are re-packed as PV A-fragments.
// PV B-fragments come from ldmatrix.x2.trans on row-major V.
#define AH 72
__global__ void __launch_bounds__(256, 2) attn_kernel(const __half* __restrict__ qkv,
                                                      const int* __restrict__ cu,
                                                      __half* __restrict__ out) {
    extern __shared__ __align__(16) __half sma[];
    __half* Qs  = sma;                         // 128*AH halves
    __half* Ksb = sma + 128 * AH;              // 2 stages of 64*AH
    __half* Vsb = sma + 128 * AH + 2 * 64 * AH;

    int qt = blockIdx.x, h = blockIdx.y, b = blockIdx.z;
    int base = cu[b];
    int len  = cu[b + 1] - base;
    int q0   = qt * 128;
    if (q0 >= len) return;
    int nq = min(128, len - q0);

    int tid = threadIdx.x;
    int lane = tid & 31, wid = tid >> 5;
    int g = lane >> 2, t4 = lane & 3;
    int qw = wid * 16;

    uint32_t qsu = smem_u32(Qs);
    uint32_t ksu[2] = { smem_u32(Ksb), smem_u32(Ksb + 64 * AH) };
    uint32_t vsu[2] = { smem_u32(Vsb), smem_u32(Vsb + 64 * AH) };

    // prologue: Q (4 groups/thread) + KV tile 0
    {
#pragma unroll
        for (int i = 0; i < 4; i++) {
            int idx = tid + i * 256;          // 0..1023
            int qi = idx >> 3, dg = idx & 7;
            uint32_t dst = qsu + (uint32_t)(qi * AH + dg * 8) * 2;
            const __half* src = qkv + (size_t)(base + q0 + qi) * 2304 + h * 64 + dg * 8;
            if (qi < nq) CP_ASYNC16(dst, src);
            else         CP_ASYNC16Z(dst, qkv);
        }
    }
    auto issueKV = [&](int t, int s) {
        int kbase = t * 64;
#pragma unroll
        for (int i = 0; i < 2; i++) {
            int idx = tid + i * 256;          // 0..511
            int j = idx >> 3, dg = idx & 7;
            int key = kbase + j;
            uint32_t off = (uint32_t)(j * AH + dg * 8) * 2;
            const __half* src = qkv + (size_t)(base + key) * 2304 + h * 64 + dg * 8;
            if (key < len) {
                CP_ASYNC16(ksu[s] + off, src + 768);
                CP_ASYNC16(vsu[s] + off, src + 1536);
            } else {
                CP_ASYNC16Z(ksu[s] + off, qkv);
                CP_ASYNC16Z(vsu[s] + off, qkv);
            }
        }
        CP_COMMIT();
    };
    issueKV(0, 0);

    float m0 = -1e30f, m1 = -1e30f, l0 = 0.f, l1 = 0.f;
    float oacc[8][4];
#pragma unroll
    for (int nf = 0; nf < 8; nf++)
#pragma unroll
        for (int r = 0; r < 4; r++) oacc[nf][r] = 0.f;

    int ntiles = (len + 63) >> 6;
    for (int t = 0; t < ntiles; t++) {
        CP_WAIT(0);
        __syncthreads();
        if (t + 1 < ntiles) issueKV(t + 1, (t + 1) & 1);

        int st = t & 1;
        const __half* Ks = Ksb + st * 64 * AH;
        int nk = min(64, len - t * 64);

        // S = Q @ K^T
        float sacc[8][4];
#pragma unroll
        for (int nf = 0; nf < 8; nf++)
#pragma unroll
            for (int r = 0; r < 4; r++) sacc[nf][r] = 0.f;
#pragma unroll
        for (int kk = 0; kk < 64; kk += 16) {
            uint32_t af[4];
            af[0] = *(const uint32_t*)&Qs[(qw + g) * AH + kk + 2 * t4];
            af[1] = *(const uint32_t*)&Qs[(qw + g + 8) * AH + kk + 2 * t4];
            af[2] = *(const uint32_t*)&Qs[(qw + g) * AH + kk + 2 * t4 + 8];
            af[3] = *(const uint32_t*)&Qs[(qw + g + 8) * AH + kk + 2 * t4 + 8];
#pragma unroll
            for (int nf = 0; nf < 8; nf++) {
                uint32_t bf[2];
                bf[0] = *(const uint32_t*)&Ks[(nf * 8 + g) * AH + kk + 2 * t4];
                bf[1] = *(const uint32_t*)&Ks[(nf * 8 + g) * AH + kk + 2 * t4 + 8];
                mma_f16(sacc[nf], af, bf);
            }
        }

        // scale + mask
#pragma unroll
        for (int nf = 0; nf < 8; nf++) {
            sacc[nf][0] *= 0.125f; sacc[nf][1] *= 0.125f;
            sacc[nf][2] *= 0.125f; sacc[nf][3] *= 0.125f;
            int j = nf * 8 + 2 * t4;
            if (j >= nk)     { sacc[nf][0] = -1e30f; sacc[nf][2] = -1e30f; }
            if (j + 1 >= nk) { sacc[nf][1] = -1e30f; sacc[nf][3] = -1e30f; }
        }

        float tm0 = -1e30f, tm1 = -1e30f;
#pragma unroll
        for (int nf = 0; nf < 8; nf++) {
            tm0 = fmaxf(tm0, fmaxf(sacc[nf][0], sacc[nf][1]));
            tm1 = fmaxf(tm1, fmaxf(sacc[nf][2], sacc[nf][3]));
        }
        tm0 = fmaxf(tm0, __shfl_xor_sync(0xffffffffu, tm0, 1));
        tm0 = fmaxf(tm0, __shfl_xor_sync(0xffffffffu, tm0, 2));
        tm1 = fmaxf(tm1, __shfl_xor_sync(0xffffffffu, tm1, 1));
        tm1 = fmaxf(tm1, __shfl_xor_sync(0xffffffffu, tm1, 2));

        float nm0 = fmaxf(m0, tm0), nm1 = fmaxf(m1, tm1);
        float sc0 = __expf(m0 - nm0), sc1 = __expf(m1 - nm1);

        // P in registers: C-frag -> A-frag identity
        uint32_t ph[8][2];
        float ls0 = 0.f, ls1 = 0.f;
#pragma unroll
        for (int nf = 0; nf < 8; nf++) {
            float p0 = __expf(sacc[nf][0] - nm0);
            float p1 = __expf(sacc[nf][1] - nm0);
            float p2 = __expf(sacc[nf][2] - nm1);
            float p3 = __expf(sacc[nf][3] - nm1);
            ls0 += p0 + p1; ls1 += p2 + p3;
            ph[nf][0] = h2u(p0, p1);
            ph[nf][1] = h2u(p2, p3);
        }
        ls0 += __shfl_xor_sync(0xffffffffu, ls0, 1);
        ls0 += __shfl_xor_sync(0xffffffffu, ls0, 2);
        ls1 += __shfl_xor_sync(0xffffffffu, ls1, 1);
        ls1 += __shfl_xor_sync(0xffffffffu, ls1, 2);
        l0 = l0 * sc0 + ls0;
        l1 = l1 * sc1 + ls1;
        m0 = nm0; m1 = nm1;

#pragma unroll
        for (int nf = 0; nf < 8; nf++) {
            oacc[nf][0] *= sc0; oacc[nf][1] *= sc0;
            oacc[nf][2] *= sc1; oacc[nf][3] *= sc1;
        }

        // O += P @ V ; V row-major, B-frags via ldmatrix.x2.trans
        uint32_t vrow = vsu[st] + (uint32_t)(((lane & 15)) * AH) * 2;
#pragma unroll
        for (int mkb = 0; mkb < 4; mkb++) {
            uint32_t af[4] = { ph[2 * mkb][0], ph[2 * mkb][1],
                               ph[2 * mkb + 1][0], ph[2 * mkb + 1][1] };
            uint32_t rbase = vrow + (uint32_t)(16 * mkb * AH) * 2;
#pragma unroll
            for (int nf = 0; nf < 8; nf++) {
                uint32_t bf[2];
                ldsm_x2_t(bf[0], bf[1], rbase + nf * 16);
                mma_f16(oacc[nf], af, bf);
            }
        }
    }

    float inv0 = 1.0f / l0, inv1 = 1.0f / l1;
    if (q0 + qw + g < base + len - base + 0 && qw + g < nq) {
        __half* op = out + (size_t)(base + q0 + qw + g) * D_ + h * 64;
#pragma unroll
        for (int nf = 0; nf < 8; nf++) {
            int cc = nf * 8 + 2 * t4;
            *(__half2*)(op + cc) = __floats2half2_rn(oacc[nf][0] * inv0, oacc[nf][1] * inv0);
        }
    }
    if (qw + g + 8 < nq) {
        __half* op = out + (size_t)(base + q0 + qw + g + 8) * D_ + h * 64;
#pragma unroll
        for (int nf = 0; nf < 8; nf++) {
            int cc = nf * 8 + 2 * t4;
            *(__half2*)(op + cc) = __floats2half2_rn(oacc[nf][2] * inv1, oacc[nf][3] * inv1);
        }
    }
}

// ---------------- host launch ----------------
extern "C" void kernel_launch(void* const* d_in, const int* in_sizes, int n_in,
                              void* d_out, int out_size) {
    const float* x     = (const float*)d_in[0];
    const int*   cu    = (const int*)  d_in[1];
    const float* g1    = (const float*)d_in[2];
    const float* beta1 = (const float*)d_in[3];
    const float* Wqkv  = (const float*)d_in[4];
    const float* bqkv  = (const float*)d_in[5];
    const float* Wo    = (const float*)d_in[6];
    const float* bo    = (const float*)d_in[7];
    const float* g2    = (const float*)d_in[8];
    const float* beta2 = (const float*)d_in[9];
    const float* W1    = (const float*)d_in[10];
    const float* b_fc1 = (const float*)d_in[11];
    const float* W2    = (const float*)d_in[12];
    const float* b_fc2 = (const float*)d_in[13];
    float* out = (float*)d_out;

    int total = in_sizes[0] / D_;   // 6144
    int nb    = in_sizes[1] - 1;    // 8

    __half *xnh, *qkvh, *attnh, *midh, *wqkvTh, *woTh, *w1Th, *w2Th;
    float  *x2;
    cudaGetSymbolAddress((void**)&xnh,    g_xnh);
    cudaGetSymbolAddress((void**)&qkvh,   g_qkvh);
    cudaGetSymbolAddress((void**)&attnh,  g_attnh);
    cudaGetSymbolAddress((void**)&x2,     g_x2);
    cudaGetSymbolAddress((void**)&midh,   g_midh);
    cudaGetSymbolAddress((void**)&wqkvTh, g_WqkvTh);
    cudaGetSymbolAddress((void**)&woTh,   g_WoTh);
    cudaGetSymbolAddress((void**)&w1Th,   g_W1Th);
    cudaGetSymbolAddress((void**)&w2Th,   g_W2Th);

    static cudaStream_t s1 = nullptr, s2 = nullptr;
    static cudaEvent_t evF = nullptr, ev1 = nullptr, ev2 = nullptr;
    if (s1 == nullptr) {
        cudaStreamCreateWithFlags(&s1, cudaStreamNonBlocking);
        cudaStreamCreateWithFlags(&s2, cudaStreamNonBlocking);
        cudaEventCreateWithFlags(&evF, cudaEventDisableTiming);
        cudaEventCreateWithFlags(&ev1, cudaEventDisableTiming);
        cudaEventCreateWithFlags(&ev2, cudaEventDisableTiming);
    }

    int mb = total / 128;
    dim3 tb(32, 8);

    const int GEMM_SMEM = 2 * 3 * STG_H * 2;           // 61440 B
    const int ATTN_SMEM = (128 * AH + 4 * 64 * AH) * 2; // 55296 B
    cudaFuncSetAttribute((const void*)tgemm<0, __half>, cudaFuncAttributeMaxDynamicSharedMemorySize, GEMM_SMEM);
    cudaFuncSetAttribute((const void*)tgemm<1, float>,  cudaFuncAttributeMaxDynamicSharedMemorySize, GEMM_SMEM);
    cudaFuncSetAttribute((const void*)tgemm<2, __half>, cudaFuncAttributeMaxDynamicSharedMemorySize, GEMM_SMEM);
    cudaFuncSetAttribute((const void*)attn_kernel,      cudaFuncAttributeMaxDynamicSharedMemorySize, ATTN_SMEM);

    // fork weight transposes onto side streams
    cudaEventRecord(evF, 0);
    cudaStreamWaitEvent(s1, evF, 0);
    cudaStreamWaitEvent(s2, evF, 0);
    transpose_h<<<dim3(3 * D_ / 32, D_ / 32), tb, 0, s1>>>(Wqkv, wqkvTh, D_, 3 * D_);
    transpose_h<<<dim3(D_ / 32, D_ / 32),     tb, 0, s1>>>(Wo,   woTh,   D_, D_);
    cudaEventRecord(ev1, s1);
    transpose_h<<<dim3(DFF_ / 32, D_ / 32),   tb, 0, s2>>>(W1,   w1Th,   D_, DFF_);
    transpose_h<<<dim3(D_ / 32, DFF_ / 32),   tb, 0, s2>>>(W2,   w2Th,   DFF_, D_);
    cudaEventRecord(ev2, s2);

    // main stream
    ln_kernel<<<total, 256>>>(x, g1, beta1, xnh);
    cudaStreamWaitEvent(0, ev1, 0);
    tgemm<0, __half><<<dim3(3 * D_ / 128, mb), 128, GEMM_SMEM>>>(
        xnh, wqkvTh, bqkv, nullptr, qkvh, total, 3 * D_, D_);
    attn_kernel<<<dim3(SMAX_ / 128, H_, nb), 256, ATTN_SMEM>>>(qkvh, cu, attnh);
    tgemm<1, float><<<dim3(D_ / 128, mb), 128, GEMM_SMEM>>>(
        attnh, woTh, bo, x, x2, total, D_, D_);
    ln_kernel<<<total, 256>>>(x2, g2, beta2, xnh);
    cudaStreamWaitEvent(0, ev2, 0);
    tgemm<2, __half><<<dim3(DFF_ / 128, mb), 128, GEMM_SMEM>>>(
        xnh, w1Th, b_fc1, nullptr, midh, total, DFF_, D_);
    tgemm<1, float><<<dim3(D_ / 128, mb), 128, GEMM_SMEM>>>(
        midh, w2Th, b_fc2, x2, out, total, D_, DFF_);
}